// round 1
// baseline (speedup 1.0000x reference)
#include <cuda_runtime.h>
#include <cuda_bf16.h>
#include <math.h>

// Problem dims (fixed per reference)
#define B_   8
#define Q_   64
#define S_   64
#define T_   64
#define H_   8
#define DH_  64
#define NH_  512
#define STAT_K_ 8
#define TOK_K_  16
#define NEGV (-1e6f)

// Scratch (device globals; allocation is forbidden)
__device__ float g_q_stat[B_ * Q_ * NH_];            // [B*Q, NH]
__device__ float g_q_tok [B_ * Q_ * NH_];            // [B*Q, NH]
__device__ float g_k_stat[B_ * S_ * NH_];            // [B*S, NH]
__device__ float g_k_tok16[B_ * S_ * TOK_K_ * NH_];  // [B*S*16, NH] last-16 tokens only
__device__ float g_v16   [B_ * S_ * TOK_K_ * NH_];   // [B*S*16, NH]
__device__ float g_attn  [B_ * Q_ * NH_];            // [B*Q, NH] (b,q,h,d) layout

// ---------------------------------------------------------------------------
// Tiled fp32 GEMM: C[M,512] = A[M(,gathered),512] @ W[512,512]
// BM=BN=64, BK=16, 256 threads, 4x4 microtile per thread.
// GATHER: logical row r -> source row (r/16)*64 + 48 + (r%16)  (last-16 tokens)
// ---------------------------------------------------------------------------
template <bool GATHER>
__global__ __launch_bounds__(256)
void gemm512(const float* __restrict__ A, const float* __restrict__ W,
             float* __restrict__ C) {
    __shared__ float As[64][17];   // padded to kill bank conflicts
    __shared__ float Ws[16][64];

    const int tx = threadIdx.x & 15;
    const int ty = threadIdx.x >> 4;
    const int rowBase = blockIdx.y * 64;
    const int colBase = blockIdx.x * 64;

    float acc[4][4];
#pragma unroll
    for (int i = 0; i < 4; i++)
#pragma unroll
        for (int j = 0; j < 4; j++) acc[i][j] = 0.f;

    for (int k0 = 0; k0 < 512; k0 += 16) {
        // Load A tile: 64x16
#pragma unroll
        for (int i = threadIdx.x; i < 64 * 16; i += 256) {
            int r = i >> 4;
            int c = i & 15;
            int gr = rowBase + r;
            int src = GATHER ? ((gr >> 4) * 64 + 48 + (gr & 15)) : gr;
            As[r][c] = A[(size_t)src * 512 + k0 + c];
        }
        // Load W tile: 16x64 (fully coalesced)
#pragma unroll
        for (int i = threadIdx.x; i < 16 * 64; i += 256) {
            int r = i >> 6;
            int c = i & 63;
            Ws[r][c] = W[(size_t)(k0 + r) * 512 + colBase + c];
        }
        __syncthreads();

#pragma unroll
        for (int kk = 0; kk < 16; kk++) {
            float a[4], w[4];
#pragma unroll
            for (int i = 0; i < 4; i++) a[i] = As[ty * 4 + i][kk];
#pragma unroll
            for (int j = 0; j < 4; j++) w[j] = Ws[kk][tx * 4 + j];
#pragma unroll
            for (int i = 0; i < 4; i++)
#pragma unroll
                for (int j = 0; j < 4; j++) acc[i][j] = fmaf(a[i], w[j], acc[i][j]);
        }
        __syncthreads();
    }

#pragma unroll
    for (int i = 0; i < 4; i++) {
        int r = rowBase + ty * 4 + i;
#pragma unroll
        for (int j = 0; j < 4; j++) {
            C[(size_t)r * 512 + colBase + tx * 4 + j] = acc[i][j];
        }
    }
}

// ---------------------------------------------------------------------------
// Fused hierarchical attention. One block per (b,h,q). 128 threads.
//   stat scores over S=64 -> valid-len mask -> top-8 select -> softmax
//   token scores over last-16 tokens of the 8 selected segments -> softmax
//   combined-weight reduction over V -> g_attn[(b,q), h*64+d]
// ---------------------------------------------------------------------------
__global__ __launch_bounds__(128)
void attn_kernel(const int* __restrict__ valid_lens) {
    const int idx = blockIdx.x;
    const int q = idx & 63;
    const int h = (idx >> 6) & 7;
    const int b = idx >> 9;
    const int tid = threadIdx.x;
    const float scale = 0.125f;  // 1/sqrt(64)

    __shared__ float qs[64], qt[64], sc[64];
    __shared__ int   sidx[8];
    __shared__ float sw[8];
    __shared__ float cw[8][16];

    if (tid < 64) {
        qs[tid] = g_q_stat[(size_t)(b * 64 + q) * 512 + h * 64 + tid];
        qt[tid] = g_q_tok [(size_t)(b * 64 + q) * 512 + h * 64 + tid];
    }
    __syncthreads();

    const int vlen = valid_lens[b];

    // --- stat scores, one thread per segment s ---
    if (tid < 64) {
        const int s = tid;
        const float* kp = &g_k_stat[(size_t)(b * 64 + s) * 512 + h * 64];
        float acc = 0.f;
#pragma unroll
        for (int d = 0; d < 64; d++) acc = fmaf(qs[d], kp[d], acc);
        sc[s] = (s < vlen) ? acc * scale : NEGV;
    }
    __syncthreads();

    // --- top-8 selection + stat softmax (serial in thread 0; 4096 blocks hide it) ---
    if (tid == 0) {
        float tmp[64];
#pragma unroll
        for (int i = 0; i < 64; i++) tmp[i] = sc[i];
        float vals[8];
        for (int j = 0; j < 8; j++) {
            int bi = 0; float bv = tmp[0];
            for (int i = 1; i < 64; i++) {
                if (tmp[i] > bv) { bv = tmp[i]; bi = i; }
            }
            sidx[j] = bi; vals[j] = bv; tmp[bi] = -3.0e38f;
        }
        const float m = vals[0];
        float e[8], sum = 0.f;
        for (int j = 0; j < 8; j++) { e[j] = expf(vals[j] - m); sum += e[j]; }
        const float inv = 1.f / sum;
        for (int j = 0; j < 8; j++) sw[j] = e[j] * inv;
    }
    __syncthreads();

    // --- token scores: 128 threads = 8 selected segments x 16 tokens ---
    {
        const int j = tid >> 4;
        const int t = tid & 15;
        const int s = sidx[j];
        const float* kp = &g_k_tok16[(((size_t)(b * 64 + s)) * 16 + t) * 512 + h * 64];
        float acc = 0.f;
#pragma unroll
        for (int d = 0; d < 64; d++) acc = fmaf(qt[d], kp[d], acc);
        cw[j][t] = acc * scale;
    }
    __syncthreads();

    // --- per-segment token softmax, fused with stat weight ---
    if (tid < 8) {
        const int j = tid;
        float m = cw[j][0];
#pragma unroll
        for (int t = 1; t < 16; t++) m = fmaxf(m, cw[j][t]);
        float e[16], sum = 0.f;
#pragma unroll
        for (int t = 0; t < 16; t++) { e[t] = expf(cw[j][t] - m); sum += e[t]; }
        const float f = sw[j] / sum;
#pragma unroll
        for (int t = 0; t < 16; t++) cw[j][t] = e[t] * f;
    }
    __syncthreads();

    // --- weighted reduction over V: one thread per head-dim d (coalesced) ---
    if (tid < 64) {
        const int d = tid;
        float acc = 0.f;
#pragma unroll
        for (int j = 0; j < 8; j++) {
            const int s = sidx[j];
            const float* vp = &g_v16[(((size_t)(b * 64 + s)) * 16) * 512 + h * 64 + d];
#pragma unroll
            for (int t = 0; t < 16; t++) acc = fmaf(cw[j][t], vp[(size_t)t * 512], acc);
        }
        g_attn[(size_t)(b * 64 + q) * 512 + h * 64 + d] = acc;
    }
}

// ---------------------------------------------------------------------------
extern "C" void kernel_launch(void* const* d_in, const int* in_sizes, int n_in,
                              void* d_out, int out_size) {
    const float* queries        = (const float*)d_in[0];
    const float* stat_keys      = (const float*)d_in[1];
    const float* token_keys     = (const float*)d_in[2];
    const float* values         = (const float*)d_in[3];
    const int*   stat_valid_len = (const int*)  d_in[4];
    const float* Wq_stat        = (const float*)d_in[5];
    const float* Wq_token       = (const float*)d_in[6];
    const float* Wk_stat        = (const float*)d_in[7];
    const float* Wk_token       = (const float*)d_in[8];
    const float* Wv             = (const float*)d_in[9];
    const float* Wo             = (const float*)d_in[10];
    float* out = (float*)d_out;

    float *q_stat, *q_tok, *k_stat, *k_tok16, *v16, *attn;
    cudaGetSymbolAddress((void**)&q_stat,  g_q_stat);
    cudaGetSymbolAddress((void**)&q_tok,   g_q_tok);
    cudaGetSymbolAddress((void**)&k_stat,  g_k_stat);
    cudaGetSymbolAddress((void**)&k_tok16, g_k_tok16);
    cudaGetSymbolAddress((void**)&v16,     g_v16);
    cudaGetSymbolAddress((void**)&attn,    g_attn);

    dim3 blk(256);
    dim3 gridSmall(512 / 64, 512 / 64);       // M=512
    dim3 gridBig(512 / 64, 8192 / 64);        // M=8192 (B*S*16)

    // Projections
    gemm512<false><<<gridSmall, blk>>>(queries,   Wq_stat,  q_stat);
    gemm512<false><<<gridSmall, blk>>>(queries,   Wq_token, q_tok);
    gemm512<false><<<gridSmall, blk>>>(stat_keys, Wk_stat,  k_stat);
    gemm512<true ><<<gridBig,   blk>>>(token_keys, Wk_token, k_tok16);
    gemm512<true ><<<gridBig,   blk>>>(values,     Wv,       v16);

    // Fused hierarchical attention
    attn_kernel<<<B_ * H_ * Q_, 128>>>(stat_valid_len);

    // Output projection
    gemm512<false><<<gridSmall, blk>>>(attn, Wo, out);
}

// round 4
// speedup vs baseline: 1.6184x; 1.6184x over previous
#include <cuda_runtime.h>
#include <cuda_bf16.h>
#include <cstdint>
#include <math.h>

#define B_   8
#define Q_   64
#define S_   64
#define T_   64
#define H_   8
#define DH_  64
#define NH_  512
#define NEGV (-1e6f)

// ---------------------------------------------------------------------------
// Scratch (device globals)
// ---------------------------------------------------------------------------
__device__ float g_q_stat[B_ * Q_ * NH_];
__device__ float g_q_tok [B_ * Q_ * NH_];
__device__ float g_k_stat[B_ * S_ * NH_];
__device__ float g_k_tok16[B_ * S_ * 16 * NH_];
__device__ float g_v16   [B_ * S_ * 16 * NH_];
__device__ float g_attn  [B_ * Q_ * NH_];
__device__ __nv_bfloat16 g_wt_hi[6 * NH_ * NH_];   // W^T [N,K] bf16 hi
__device__ __nv_bfloat16 g_wt_lo[6 * NH_ * NH_];   // W^T [N,K] bf16 lo
__device__ float g_wtf_hi[2 * NH_ * NH_];          // W^T [N,K] tf32 hi (w0, w2)
__device__ float g_wtf_lo[2 * NH_ * NH_];          // W^T [N,K] tf32 lo

__device__ __forceinline__ uint32_t smem_u32(const void* p) {
    uint32_t a;
    asm("{ .reg .u64 t; cvta.to.shared.u64 t, %1; cvt.u32.u64 %0, t; }" : "=r"(a) : "l"(p));
    return a;
}
__device__ __forceinline__ void ldsm_x4(uint32_t* r, uint32_t addr) {
    asm volatile("ldmatrix.sync.aligned.m8n8.x4.shared.b16 {%0,%1,%2,%3}, [%4];"
        : "=r"(r[0]), "=r"(r[1]), "=r"(r[2]), "=r"(r[3]) : "r"(addr));
}
__device__ __forceinline__ void ldsm_x2(uint32_t* r, uint32_t addr) {
    asm volatile("ldmatrix.sync.aligned.m8n8.x2.shared.b16 {%0,%1}, [%2];"
        : "=r"(r[0]), "=r"(r[1]) : "r"(addr));
}
__device__ __forceinline__ void mma16816(float* d, const uint32_t* a, const uint32_t* b) {
    asm volatile("mma.sync.aligned.m16n8k16.row.col.f32.bf16.bf16.f32 "
        "{%0,%1,%2,%3}, {%4,%5,%6,%7}, {%8,%9}, {%0,%1,%2,%3};"
        : "+f"(d[0]), "+f"(d[1]), "+f"(d[2]), "+f"(d[3])
        : "r"(a[0]), "r"(a[1]), "r"(a[2]), "r"(a[3]), "r"(b[0]), "r"(b[1]));
}
__device__ __forceinline__ void mma_tf32(float* d, const uint32_t* a, const uint32_t* b) {
    asm volatile("mma.sync.aligned.m16n8k8.row.col.f32.tf32.tf32.f32 "
        "{%0,%1,%2,%3}, {%4,%5,%6,%7}, {%8,%9}, {%0,%1,%2,%3};"
        : "+f"(d[0]), "+f"(d[1]), "+f"(d[2]), "+f"(d[3])
        : "r"(a[0]), "r"(a[1]), "r"(a[2]), "r"(a[3]), "r"(b[0]), "r"(b[1]));
}
__device__ __forceinline__ float tf32r(float x) {
    float r;
    asm("cvt.rna.tf32.f32 %0, %1;" : "=f"(r) : "f"(x));
    return r;
}
__device__ __forceinline__ uint32_t f2u(float x) { return __float_as_uint(x); }

// ---------------------------------------------------------------------------
// Prep: transpose W[K,N] fp32 -> Wt[N,K] bf16 hi + lo, all 6 weights
// ---------------------------------------------------------------------------
struct WPtrs { const float* p[6]; };

__global__ __launch_bounds__(256)
void prep_w(WPtrs ws, __nv_bfloat16* __restrict__ hi, __nv_bfloat16* __restrict__ lo) {
    __shared__ float t[32][33];
    const int widx = blockIdx.z;
    const float* W = ws.p[widx];
    __nv_bfloat16* hiw = hi + (size_t)widx * NH_ * NH_;
    __nv_bfloat16* low = lo + (size_t)widx * NH_ * NH_;
    const int n0 = blockIdx.x * 32, k0 = blockIdx.y * 32;
    const int tx = threadIdx.x, ty = threadIdx.y;
#pragma unroll
    for (int i = ty; i < 32; i += 8)
        t[i][tx] = W[(size_t)(k0 + i) * NH_ + n0 + tx];
    __syncthreads();
#pragma unroll
    for (int i = ty; i < 32; i += 8) {
        float v = t[tx][i];
        __nv_bfloat16 h = __float2bfloat16(v);
        hiw[(size_t)(n0 + i) * NH_ + k0 + tx] = h;
        low[(size_t)(n0 + i) * NH_ + k0 + tx] = __float2bfloat16(v - __bfloat162float(h));
    }
}

// Prep: transpose W[K,N] -> Wt[N,K] tf32 hi + lo (fp32 storage).
// z=0 -> Wq_stat (w0), z=1 -> Wk_stat (w2)
__global__ __launch_bounds__(256)
void prep_wtf(const float* __restrict__ W0, const float* __restrict__ W2,
              float* __restrict__ hi, float* __restrict__ lo) {
    __shared__ float t[32][33];
    const int z = blockIdx.z;
    const float* W = z ? W2 : W0;
    float* hiw = hi + (size_t)z * NH_ * NH_;
    float* low = lo + (size_t)z * NH_ * NH_;
    const int n0 = blockIdx.x * 32, k0 = blockIdx.y * 32;
    const int tx = threadIdx.x, ty = threadIdx.y;
#pragma unroll
    for (int i = ty; i < 32; i += 8)
        t[i][tx] = W[(size_t)(k0 + i) * NH_ + n0 + tx];
    __syncthreads();
#pragma unroll
    for (int i = ty; i < 32; i += 8) {
        float v = t[tx][i];
        float h = tf32r(v);
        hiw[(size_t)(n0 + i) * NH_ + k0 + tx] = h;
        low[(size_t)(n0 + i) * NH_ + k0 + tx] = tf32r(v - h);
    }
}

// ---------------------------------------------------------------------------
// bf16 3-term mma.sync GEMM (smooth paths). CTA tile BMx128, 256 threads.
// ---------------------------------------------------------------------------
template <int BM, bool GATHER>
__global__ __launch_bounds__(256, 2)
void gemm_mma(const float* __restrict__ A,
              const __nv_bfloat16* __restrict__ Bhi,
              const __nv_bfloat16* __restrict__ Blo,
              float* __restrict__ C) {
    constexpr int MT = BM / 32;
    constexpr int P  = 40;
    __shared__ __nv_bfloat16 sAh[BM * P], sAl[BM * P], sBh[128 * P], sBl[128 * P];

    const int tid = threadIdx.x;
    const int wid = tid >> 5, lane = tid & 31;
    const int wm = wid >> 2, wn = wid & 3;
    const int m0 = blockIdx.y * BM, n0 = blockIdx.x * 128;

    const uint32_t aAh = smem_u32(sAh), aAl = smem_u32(sAl);
    const uint32_t aBh = smem_u32(sBh), aBl = smem_u32(sBl);

    const uint32_t rowA = (uint32_t)(wm * (MT * 16) + (lane & 7) + ((lane >> 3) & 1) * 8);
    const uint32_t colA = (uint32_t)(((lane >> 4) & 1) * 16);
    const uint32_t adAh = aAh + rowA * 80 + colA;
    const uint32_t adAl = aAl + rowA * 80 + colA;
    const uint32_t rowB = (uint32_t)(wn * 32 + (lane & 7));
    const uint32_t colB = (uint32_t)(((lane >> 3) & 1) * 16);
    const uint32_t adBh = aBh + rowB * 80 + colB;
    const uint32_t adBl = aBl + rowB * 80 + colB;

    float acc[MT][4][4];
#pragma unroll
    for (int i = 0; i < MT; i++)
#pragma unroll
        for (int j = 0; j < 4; j++)
#pragma unroll
            for (int e = 0; e < 4; e++) acc[i][j][e] = 0.f;

    for (int kc = 0; kc < 16; kc++) {
        const int k0 = kc * 32;
#pragma unroll
        for (int i = 0; i < BM * 8 / 256; i++) {
            int idx = tid + i * 256;
            int r = idx >> 3, c4 = idx & 7;
            int gr = m0 + r;
            int src = GATHER ? ((gr >> 4) * 64 + 48 + (gr & 15)) : gr;
            float4 v = *(const float4*)&A[(size_t)src * NH_ + k0 + c4 * 4];
            __nv_bfloat16 h0 = __float2bfloat16(v.x), h1 = __float2bfloat16(v.y),
                          h2 = __float2bfloat16(v.z), h3 = __float2bfloat16(v.w);
            __nv_bfloat16 l0 = __float2bfloat16(v.x - __bfloat162float(h0)),
                          l1 = __float2bfloat16(v.y - __bfloat162float(h1)),
                          l2 = __float2bfloat16(v.z - __bfloat162float(h2)),
                          l3 = __float2bfloat16(v.w - __bfloat162float(h3));
            uint2 hh, ll;
            hh.x = (uint32_t)__bfloat16_as_ushort(h0) | ((uint32_t)__bfloat16_as_ushort(h1) << 16);
            hh.y = (uint32_t)__bfloat16_as_ushort(h2) | ((uint32_t)__bfloat16_as_ushort(h3) << 16);
            ll.x = (uint32_t)__bfloat16_as_ushort(l0) | ((uint32_t)__bfloat16_as_ushort(l1) << 16);
            ll.y = (uint32_t)__bfloat16_as_ushort(l2) | ((uint32_t)__bfloat16_as_ushort(l3) << 16);
            *(uint2*)((char*)sAh + r * 80 + c4 * 8) = hh;
            *(uint2*)((char*)sAl + r * 80 + c4 * 8) = ll;
        }
#pragma unroll
        for (int i = 0; i < 2; i++) {
            int idx = tid + i * 256;
            int r = idx >> 2, q = idx & 3;
            *(uint4*)((char*)sBh + r * 80 + q * 16) =
                *(const uint4*)&Bhi[(size_t)(n0 + r) * NH_ + k0 + q * 8];
            *(uint4*)((char*)sBl + r * 80 + q * 16) =
                *(const uint4*)&Blo[(size_t)(n0 + r) * NH_ + k0 + q * 8];
        }
        __syncthreads();

#pragma unroll
        for (int ks = 0; ks < 2; ks++) {
            uint32_t a[MT][4], b[4][2];
#pragma unroll
            for (int mi = 0; mi < MT; mi++) ldsm_x4(a[mi], adAh + mi * 1280 + ks * 32);
#pragma unroll
            for (int ni = 0; ni < 4; ni++) ldsm_x2(b[ni], adBh + ni * 640 + ks * 32);
#pragma unroll
            for (int mi = 0; mi < MT; mi++)
#pragma unroll
                for (int ni = 0; ni < 4; ni++) mma16816(acc[mi][ni], a[mi], b[ni]);
#pragma unroll
            for (int mi = 0; mi < MT; mi++) ldsm_x4(a[mi], adAl + mi * 1280 + ks * 32);
#pragma unroll
            for (int mi = 0; mi < MT; mi++)
#pragma unroll
                for (int ni = 0; ni < 4; ni++) mma16816(acc[mi][ni], a[mi], b[ni]);
#pragma unroll
            for (int mi = 0; mi < MT; mi++) ldsm_x4(a[mi], adAh + mi * 1280 + ks * 32);
#pragma unroll
            for (int ni = 0; ni < 4; ni++) ldsm_x2(b[ni], adBl + ni * 640 + ks * 32);
#pragma unroll
            for (int mi = 0; mi < MT; mi++)
#pragma unroll
                for (int ni = 0; ni < 4; ni++) mma16816(acc[mi][ni], a[mi], b[ni]);
        }
        __syncthreads();
    }

    const int mrow = m0 + wm * (MT * 16) + (lane >> 2);
    const int ncol = n0 + wn * 32 + (lane & 3) * 2;
#pragma unroll
    for (int mi = 0; mi < MT; mi++) {
#pragma unroll
        for (int ni = 0; ni < 4; ni++) {
            int col = ncol + ni * 8;
            int r0 = mrow + mi * 16;
            *(float2*)&C[(size_t)r0 * NH_ + col]       = make_float2(acc[mi][ni][0], acc[mi][ni][1]);
            *(float2*)&C[(size_t)(r0 + 8) * NH_ + col] = make_float2(acc[mi][ni][2], acc[mi][ni][3]);
        }
    }
}

// ---------------------------------------------------------------------------
// tf32 4-term split GEMM (selection-critical stat path, near-fp32 accuracy).
// CTA tile 64x64, 256 threads (8 warps, 4m x 2n), warp tile 16x32.
// z = 0: q_stat = queries @ Wq_stat ; z = 1: k_stat = stat_keys @ Wk_stat.
// ---------------------------------------------------------------------------
struct TfArgs { const float* A[2]; const float* Bh[2]; const float* Bl[2]; float* C[2]; };

__global__ __launch_bounds__(256, 2)
void gemm_tf32(TfArgs args) {
    const int z = blockIdx.z;
    const float* A  = args.A[z];
    const float* Bh = args.Bh[z];
    const float* Bl = args.Bl[z];
    float* C        = args.C[z];

    __shared__ __align__(16) float sAh[64 * 36], sAl[64 * 36], sBh[64 * 36], sBl[64 * 36];
    const int tid = threadIdx.x, wid = tid >> 5, lane = tid & 31;
    const int wm = wid >> 1, wn = wid & 1;
    const int m0 = blockIdx.y * 64, n0 = blockIdx.x * 64;

    float acc[4][4];
#pragma unroll
    for (int i = 0; i < 4; i++)
#pragma unroll
        for (int j = 0; j < 4; j++) acc[i][j] = 0.f;

    for (int kc = 0; kc < 16; kc++) {
        const int k0 = kc * 32;
#pragma unroll
        for (int i = 0; i < 2; i++) {
            int idx = tid + i * 256;
            int r = idx >> 3, c4 = idx & 7;
            float4 v = *(const float4*)&A[(size_t)(m0 + r) * NH_ + k0 + c4 * 4];
            float4 h, l;
            h.x = tf32r(v.x); l.x = tf32r(v.x - h.x);
            h.y = tf32r(v.y); l.y = tf32r(v.y - h.y);
            h.z = tf32r(v.z); l.z = tf32r(v.z - h.z);
            h.w = tf32r(v.w); l.w = tf32r(v.w - h.w);
            *(float4*)&sAh[r * 36 + c4 * 4] = h;
            *(float4*)&sAl[r * 36 + c4 * 4] = l;
            *(float4*)&sBh[r * 36 + c4 * 4] = *(const float4*)&Bh[(size_t)(n0 + r) * NH_ + k0 + c4 * 4];
            *(float4*)&sBl[r * 36 + c4 * 4] = *(const float4*)&Bl[(size_t)(n0 + r) * NH_ + k0 + c4 * 4];
        }
        __syncthreads();

#pragma unroll
        for (int kk = 0; kk < 4; kk++) {
            const int cb = kk * 8 + (lane & 3);
            const int ar = wm * 16 + (lane >> 2);
            uint32_t ah[4], al[4];
            ah[0] = f2u(sAh[ar * 36 + cb]);        ah[1] = f2u(sAh[(ar + 8) * 36 + cb]);
            ah[2] = f2u(sAh[ar * 36 + cb + 4]);    ah[3] = f2u(sAh[(ar + 8) * 36 + cb + 4]);
            al[0] = f2u(sAl[ar * 36 + cb]);        al[1] = f2u(sAl[(ar + 8) * 36 + cb]);
            al[2] = f2u(sAl[ar * 36 + cb + 4]);    al[3] = f2u(sAl[(ar + 8) * 36 + cb + 4]);
#pragma unroll
            for (int ni = 0; ni < 4; ni++) {
                const int br = wn * 32 + ni * 8 + (lane >> 2);
                uint32_t bh[2], bl[2];
                bh[0] = f2u(sBh[br * 36 + cb]);
                bh[1] = f2u(sBh[br * 36 + cb + 4]);
                bl[0] = f2u(sBl[br * 36 + cb]);
                bl[1] = f2u(sBl[br * 36 + cb + 4]);
                mma_tf32(acc[ni], ah, bh);
                mma_tf32(acc[ni], al, bh);
                mma_tf32(acc[ni], ah, bl);
                mma_tf32(acc[ni], al, bl);
            }
        }
        __syncthreads();
    }

    const int row = m0 + wm * 16 + (lane >> 2);
    const int col0 = n0 + wn * 32 + (lane & 3) * 2;
#pragma unroll
    for (int ni = 0; ni < 4; ni++) {
        *(float2*)&C[(size_t)row * NH_ + col0 + ni * 8]       = make_float2(acc[ni][0], acc[ni][1]);
        *(float2*)&C[(size_t)(row + 8) * NH_ + col0 + ni * 8] = make_float2(acc[ni][2], acc[ni][3]);
    }
}

// ---------------------------------------------------------------------------
// Fused hierarchical attention (validated in round 1)
// ---------------------------------------------------------------------------
__global__ __launch_bounds__(128)
void attn_kernel(const int* __restrict__ valid_lens) {
    const int idx = blockIdx.x;
    const int q = idx & 63;
    const int h = (idx >> 6) & 7;
    const int b = idx >> 9;
    const int tid = threadIdx.x;
    const float scale = 0.125f;

    __shared__ float qs[64], qt[64], sc[64];
    __shared__ int   sidx[8];
    __shared__ float sw[8];
    __shared__ float cw[8][16];

    if (tid < 64) {
        qs[tid] = g_q_stat[(size_t)(b * 64 + q) * 512 + h * 64 + tid];
        qt[tid] = g_q_tok [(size_t)(b * 64 + q) * 512 + h * 64 + tid];
    }
    __syncthreads();

    const int vlen = valid_lens[b];

    if (tid < 64) {
        const int s = tid;
        const float* kp = &g_k_stat[(size_t)(b * 64 + s) * 512 + h * 64];
        float acc = 0.f;
#pragma unroll
        for (int d = 0; d < 64; d++) acc = fmaf(qs[d], kp[d], acc);
        sc[s] = (s < vlen) ? acc * scale : NEGV;
    }
    __syncthreads();

    if (tid == 0) {
        float tmp[64];
#pragma unroll
        for (int i = 0; i < 64; i++) tmp[i] = sc[i];
        float vals[8];
        for (int j = 0; j < 8; j++) {
            int bi = 0; float bv = tmp[0];
            for (int i = 1; i < 64; i++) {
                if (tmp[i] > bv) { bv = tmp[i]; bi = i; }
            }
            sidx[j] = bi; vals[j] = bv; tmp[bi] = -3.0e38f;
        }
        const float m = vals[0];
        float e[8], sum = 0.f;
        for (int j = 0; j < 8; j++) { e[j] = expf(vals[j] - m); sum += e[j]; }
        const float inv = 1.f / sum;
        for (int j = 0; j < 8; j++) sw[j] = e[j] * inv;
    }
    __syncthreads();

    {
        const int j = tid >> 4;
        const int t = tid & 15;
        const int s = sidx[j];
        const float* kp = &g_k_tok16[(((size_t)(b * 64 + s)) * 16 + t) * 512 + h * 64];
        float acc = 0.f;
#pragma unroll
        for (int d = 0; d < 64; d++) acc = fmaf(qt[d], kp[d], acc);
        cw[j][t] = acc * scale;
    }
    __syncthreads();

    if (tid < 8) {
        const int j = tid;
        float m = cw[j][0];
#pragma unroll
        for (int t = 1; t < 16; t++) m = fmaxf(m, cw[j][t]);
        float e[16], sum = 0.f;
#pragma unroll
        for (int t = 0; t < 16; t++) { e[t] = expf(cw[j][t] - m); sum += e[t]; }
        const float f = sw[j] / sum;
#pragma unroll
        for (int t = 0; t < 16; t++) cw[j][t] = e[t] * f;
    }
    __syncthreads();

    if (tid < 64) {
        const int d = tid;
        float acc = 0.f;
#pragma unroll
        for (int j = 0; j < 8; j++) {
            const int s = sidx[j];
            const float* vp = &g_v16[(((size_t)(b * 64 + s)) * 16) * 512 + h * 64 + d];
#pragma unroll
            for (int t = 0; t < 16; t++) acc = fmaf(cw[j][t], vp[(size_t)t * 512], acc);
        }
        g_attn[(size_t)(b * 64 + q) * 512 + h * 64 + d] = acc;
    }
}

// ---------------------------------------------------------------------------
extern "C" void kernel_launch(void* const* d_in, const int* in_sizes, int n_in,
                              void* d_out, int out_size) {
    const float* queries        = (const float*)d_in[0];
    const float* stat_keys      = (const float*)d_in[1];
    const float* token_keys     = (const float*)d_in[2];
    const float* values         = (const float*)d_in[3];
    const int*   stat_valid_len = (const int*)  d_in[4];
    WPtrs ws;
    for (int i = 0; i < 6; i++) ws.p[i] = (const float*)d_in[5 + i];
    float* out = (float*)d_out;

    float *q_stat, *q_tok, *k_stat, *k_tok16, *v16, *attn;
    __nv_bfloat16 *wt_hi, *wt_lo;
    float *wtf_hi, *wtf_lo;
    cudaGetSymbolAddress((void**)&q_stat,  g_q_stat);
    cudaGetSymbolAddress((void**)&q_tok,   g_q_tok);
    cudaGetSymbolAddress((void**)&k_stat,  g_k_stat);
    cudaGetSymbolAddress((void**)&k_tok16, g_k_tok16);
    cudaGetSymbolAddress((void**)&v16,     g_v16);
    cudaGetSymbolAddress((void**)&attn,    g_attn);
    cudaGetSymbolAddress((void**)&wt_hi,   g_wt_hi);
    cudaGetSymbolAddress((void**)&wt_lo,   g_wt_lo);
    cudaGetSymbolAddress((void**)&wtf_hi,  g_wtf_hi);
    cudaGetSymbolAddress((void**)&wtf_lo,  g_wtf_lo);

    const size_t WSZ = (size_t)NH_ * NH_;

    // 1) weight prep
    prep_w  <<<dim3(16, 16, 6), dim3(32, 8)>>>(ws, wt_hi, wt_lo);
    prep_wtf<<<dim3(16, 16, 2), dim3(32, 8)>>>(ws.p[0], ws.p[2], wtf_hi, wtf_lo);

    // 2) selection-critical stat projections (tf32 4-term, near-fp32)
    TfArgs ta;
    ta.A[0] = queries;   ta.Bh[0] = wtf_hi;       ta.Bl[0] = wtf_lo;       ta.C[0] = q_stat;
    ta.A[1] = stat_keys; ta.Bh[1] = wtf_hi + WSZ; ta.Bl[1] = wtf_lo + WSZ; ta.C[1] = k_stat;
    gemm_tf32<<<dim3(8, 8, 2), 256>>>(ta);

    // 3) smooth-path projections (bf16 3-term)
    gemm_mma<64,  false><<<dim3(4, 8),  256>>>(queries,    wt_hi + 1 * WSZ, wt_lo + 1 * WSZ, q_tok);
    gemm_mma<128, true ><<<dim3(4, 64), 256>>>(token_keys, wt_hi + 3 * WSZ, wt_lo + 3 * WSZ, k_tok16);
    gemm_mma<128, true ><<<dim3(4, 64), 256>>>(values,     wt_hi + 4 * WSZ, wt_lo + 4 * WSZ, v16);

    // 4) fused hierarchical attention
    attn_kernel<<<B_ * H_ * Q_, 128>>>(stat_valid_len);

    // 5) output projection
    gemm_mma<64, false><<<dim3(4, 8), 256>>>(attn, wt_hi + 5 * WSZ, wt_lo + 5 * WSZ, out);
}

// round 5
// speedup vs baseline: 1.7769x; 1.0979x over previous
#include <cuda_runtime.h>
#include <cuda_fp16.h>
#include <cstdint>
#include <math.h>

#define B_   8
#define Q_   64
#define S_   64
#define T_   64
#define H_   8
#define DH_  64
#define NH_  512
#define NEGV (-1e6f)

// ---------------------------------------------------------------------------
// Scratch (device globals)
// ---------------------------------------------------------------------------
// fp16 hi/lo converted inputs
__device__ __half g_cq_h [512 * 512],  g_cq_l [512 * 512];    // queries
__device__ __half g_csk_h[512 * 512],  g_csk_l[512 * 512];    // stat_keys
__device__ __half g_ctk_h[8192 * 512], g_ctk_l[8192 * 512];   // gathered token_keys
__device__ __half g_cv_h [8192 * 512], g_cv_l [8192 * 512];   // gathered values
// fp16 hi/lo transposed weights [6][N=512][K=512]
__device__ __half g_wh[6 * 512 * 512], g_wl[6 * 512 * 512];
// fp32 GEMM outputs
__device__ float g_q_stat[512 * 512];
__device__ float g_q_tok [512 * 512];
__device__ float g_k_stat[512 * 512];
__device__ float g_k_tok [8192 * 512];
__device__ float g_vp    [8192 * 512];
// attention output (fp16 hi/lo, feeds Wo GEMM)
__device__ __half g_at_h[512 * 512], g_at_l[512 * 512];

// ---------------------------------------------------------------------------
// helpers
// ---------------------------------------------------------------------------
__device__ __forceinline__ uint32_t smem_u32(const void* p) {
    uint32_t a;
    asm("{ .reg .u64 t; cvta.to.shared.u64 t, %1; cvt.u32.u64 %0, t; }" : "=r"(a) : "l"(p));
    return a;
}
__device__ __forceinline__ void ldsm_x4(uint32_t* r, uint32_t addr) {
    asm volatile("ldmatrix.sync.aligned.m8n8.x4.shared.b16 {%0,%1,%2,%3}, [%4];"
        : "=r"(r[0]), "=r"(r[1]), "=r"(r[2]), "=r"(r[3]) : "r"(addr));
}
__device__ __forceinline__ void ldsm_x2(uint32_t* r, uint32_t addr) {
    asm volatile("ldmatrix.sync.aligned.m8n8.x2.shared.b16 {%0,%1}, [%2];"
        : "=r"(r[0]), "=r"(r[1]) : "r"(addr));
}
__device__ __forceinline__ void mma16816(float* d, const uint32_t* a, const uint32_t* b) {
    asm volatile("mma.sync.aligned.m16n8k16.row.col.f32.f16.f16.f32 "
        "{%0,%1,%2,%3}, {%4,%5,%6,%7}, {%8,%9}, {%0,%1,%2,%3};"
        : "+f"(d[0]), "+f"(d[1]), "+f"(d[2]), "+f"(d[3])
        : "r"(a[0]), "r"(a[1]), "r"(a[2]), "r"(a[3]), "r"(b[0]), "r"(b[1]));
}
__device__ __forceinline__ void cp16(uint32_t dst, const void* src) {
    asm volatile("cp.async.cg.shared.global [%0], [%1], 16;" :: "r"(dst), "l"(src));
}
#define CP_COMMIT() asm volatile("cp.async.commit_group;" ::: "memory")
#define CP_WAIT1()  asm volatile("cp.async.wait_group 1;" ::: "memory")
#define CP_WAIT0()  asm volatile("cp.async.wait_group 0;" ::: "memory")

// ---------------------------------------------------------------------------
// Convert inputs: fp32 -> fp16 hi/lo (with token gather for z>=2)
// z: 0=queries(512r), 1=stat_keys(512r), 2=token_keys gathered(8192r), 3=values gathered(8192r)
// ---------------------------------------------------------------------------
__global__ __launch_bounds__(256)
void conv_act(const float* __restrict__ q, const float* __restrict__ sk,
              const float* __restrict__ tk, const float* __restrict__ v) {
    const int z = blockIdx.y;
    const int rows = (z < 2) ? 512 : 8192;
    const int idx = blockIdx.x * 256 + threadIdx.x;      // unit = 4 floats
    if (idx >= rows * 128) return;
    const int r = idx >> 7, c4 = idx & 127;
    const float* src;
    __half *dh, *dl;
    int sr = r;
    if (z == 0)      { src = q;  dh = g_cq_h;  dl = g_cq_l; }
    else if (z == 1) { src = sk; dh = g_csk_h; dl = g_csk_l; }
    else {
        sr = (r >> 4) * 64 + 48 + (r & 15);
        if (z == 2)  { src = tk; dh = g_ctk_h; dl = g_ctk_l; }
        else         { src = v;  dh = g_cv_h;  dl = g_cv_l; }
    }
    float4 x = *(const float4*)&src[(size_t)sr * 512 + c4 * 4];
    __half h0 = __float2half(x.x), h1 = __float2half(x.y),
           h2 = __float2half(x.z), h3 = __float2half(x.w);
    __half l0 = __float2half(x.x - __half2float(h0)),
           l1 = __float2half(x.y - __half2float(h1)),
           l2 = __float2half(x.z - __half2float(h2)),
           l3 = __float2half(x.w - __half2float(h3));
    uint2 hh, ll;
    hh.x = (uint32_t)__half_as_ushort(h0) | ((uint32_t)__half_as_ushort(h1) << 16);
    hh.y = (uint32_t)__half_as_ushort(h2) | ((uint32_t)__half_as_ushort(h3) << 16);
    ll.x = (uint32_t)__half_as_ushort(l0) | ((uint32_t)__half_as_ushort(l1) << 16);
    ll.y = (uint32_t)__half_as_ushort(l2) | ((uint32_t)__half_as_ushort(l3) << 16);
    *(uint2*)&dh[(size_t)r * 512 + c4 * 4] = hh;
    *(uint2*)&dl[(size_t)r * 512 + c4 * 4] = ll;
}

// ---------------------------------------------------------------------------
// Weight prep: transpose W[K,N] fp32 -> Wt[N,K] fp16 hi/lo (6 weights)
// ---------------------------------------------------------------------------
struct WPtrs { const float* p[6]; };

__global__ __launch_bounds__(256)
void prep_w(WPtrs ws) {
    __shared__ float t[32][33];
    const int widx = blockIdx.z;
    const float* W = ws.p[widx];
    __half* hiw = g_wh + (size_t)widx * 512 * 512;
    __half* low = g_wl + (size_t)widx * 512 * 512;
    const int n0 = blockIdx.x * 32, k0 = blockIdx.y * 32;
    const int tx = threadIdx.x, ty = threadIdx.y;
#pragma unroll
    for (int i = ty; i < 32; i += 8)
        t[i][tx] = W[(size_t)(k0 + i) * 512 + n0 + tx];
    __syncthreads();
#pragma unroll
    for (int i = ty; i < 32; i += 8) {
        float v = t[tx][i];
        __half h = __float2half(v);
        hiw[(size_t)(n0 + i) * 512 + k0 + tx] = h;
        low[(size_t)(n0 + i) * 512 + k0 + tx] = __float2half(v - __half2float(h));
    }
}

// ---------------------------------------------------------------------------
// fp16 3-term hi/lo GEMM, cp.async 2-stage pipeline.
// C[M, 512(+512)] = A[M,512] @ B[N,512]^T, fp32 accum.
// CTA tile BM x 128, 256 threads (2x4 warps), warp tile (BM/2) x 32.
// SPLIT: output cols [0,512)->C0, [512,1024)->C1.
// ---------------------------------------------------------------------------
template <int BM, bool SPLIT>
__global__ __launch_bounds__(256)
void gemm16(const __half* __restrict__ Ah, const __half* __restrict__ Al,
            const __half* __restrict__ Bh, const __half* __restrict__ Bl,
            float* __restrict__ C0, float* __restrict__ C1) {
    constexpr int MT = BM / 32;
    constexpr uint32_t ABYTES = BM * 80;        // one A tile (hi or lo), pitch 80B/32-half row
    constexpr uint32_t BBYTES = 128 * 80;
    constexpr uint32_t STG    = 2 * ABYTES + 2 * BBYTES;
    extern __shared__ char smem[];
    const uint32_t sb = smem_u32(smem);

    const int tid = threadIdx.x;
    const int wid = tid >> 5, lane = tid & 31;
    const int wm = wid >> 2, wn = wid & 3;
    const int m0 = blockIdx.y * BM, n0 = blockIdx.x * 128;

    // ldmatrix base offsets (within a stage)
    const uint32_t rowA = (uint32_t)(wm * (MT * 16) + (lane & 7) + ((lane >> 3) & 1) * 8);
    const uint32_t colA = (uint32_t)(((lane >> 4) & 1) * 16);
    const uint32_t oAh = rowA * 80 + colA;
    const uint32_t oAl = oAh + ABYTES;
    const uint32_t rowB = (uint32_t)(wn * 32 + (lane & 7));
    const uint32_t colB = (uint32_t)(((lane >> 3) & 1) * 16);
    const uint32_t oBh = 2 * ABYTES + rowB * 80 + colB;
    const uint32_t oBl = oBh + BBYTES;

    float acc[MT][4][4];
#pragma unroll
    for (int i = 0; i < MT; i++)
#pragma unroll
        for (int j = 0; j < 4; j++)
#pragma unroll
            for (int e = 0; e < 4; e++) acc[i][j][e] = 0.f;

    // ---- stage loader ----
    auto load_stage = [&](int st, int kc) {
        const int k0 = kc * 32;
        const uint32_t base = sb + st * STG;
#pragma unroll
        for (int i = 0; i < BM / 64; i++) {              // A: BM*4 chunks of 16B
            int c = tid + i * 256;
            int r = c >> 2, qq = c & 3;
            uint32_t dst = base + r * 80 + qq * 16;
            const size_t gofs = (size_t)(m0 + r) * 512 + k0 + qq * 8;
            cp16(dst, Ah + gofs);
            cp16(dst + ABYTES, Al + gofs);
        }
#pragma unroll
        for (int i = 0; i < 2; i++) {                    // B: 512 chunks of 16B
            int c = tid + i * 256;
            int r = c >> 2, qq = c & 3;
            uint32_t dst = base + 2 * ABYTES + r * 80 + qq * 16;
            const size_t gofs = (size_t)(n0 + r) * 512 + k0 + qq * 8;
            cp16(dst, Bh + gofs);
            cp16(dst + BBYTES, Bl + gofs);
        }
    };

    load_stage(0, 0); CP_COMMIT();
    load_stage(1, 1); CP_COMMIT();

    for (int kc = 0; kc < 16; kc++) {
        if (kc < 15) { CP_WAIT1(); } else { CP_WAIT0(); }
        __syncthreads();
        const uint32_t so = sb + (kc & 1) * STG;
#pragma unroll
        for (int ks = 0; ks < 2; ks++) {
            uint32_t a[MT][4], b[4][2];
            // term 1: A_hi * B_hi
#pragma unroll
            for (int mi = 0; mi < MT; mi++) ldsm_x4(a[mi], so + oAh + mi * 1280 + ks * 32);
#pragma unroll
            for (int ni = 0; ni < 4; ni++) ldsm_x2(b[ni], so + oBh + ni * 640 + ks * 32);
#pragma unroll
            for (int mi = 0; mi < MT; mi++)
#pragma unroll
                for (int ni = 0; ni < 4; ni++) mma16816(acc[mi][ni], a[mi], b[ni]);
            // term 2: A_lo * B_hi
#pragma unroll
            for (int mi = 0; mi < MT; mi++) ldsm_x4(a[mi], so + oAl + mi * 1280 + ks * 32);
#pragma unroll
            for (int mi = 0; mi < MT; mi++)
#pragma unroll
                for (int ni = 0; ni < 4; ni++) mma16816(acc[mi][ni], a[mi], b[ni]);
            // term 3: A_hi * B_lo
#pragma unroll
            for (int mi = 0; mi < MT; mi++) ldsm_x4(a[mi], so + oAh + mi * 1280 + ks * 32);
#pragma unroll
            for (int ni = 0; ni < 4; ni++) ldsm_x2(b[ni], so + oBl + ni * 640 + ks * 32);
#pragma unroll
            for (int mi = 0; mi < MT; mi++)
#pragma unroll
                for (int ni = 0; ni < 4; ni++) mma16816(acc[mi][ni], a[mi], b[ni]);
        }
        __syncthreads();
        if (kc + 2 < 16) { load_stage(kc & 1, kc + 2); }
        CP_COMMIT();
    }

    // ---- epilogue ----
    const int mrow = m0 + wm * (MT * 16) + (lane >> 2);
    const int ncol = n0 + wn * 32 + (lane & 3) * 2;
#pragma unroll
    for (int mi = 0; mi < MT; mi++) {
#pragma unroll
        for (int ni = 0; ni < 4; ni++) {
            int col = ncol + ni * 8;
            float* dst;
            if (SPLIT) dst = (col < 512) ? (C0 + col) : (C1 + col - 512);
            else       dst = C0 + col;
            int r0 = mrow + mi * 16;
            *(float2*)&dst[(size_t)r0 * 512]       = make_float2(acc[mi][ni][0], acc[mi][ni][1]);
            *(float2*)&dst[(size_t)(r0 + 8) * 512] = make_float2(acc[mi][ni][2], acc[mi][ni][3]);
        }
    }
}

// ---------------------------------------------------------------------------
// Fused hierarchical attention; writes fp16 hi/lo for the Wo GEMM.
// ---------------------------------------------------------------------------
__global__ __launch_bounds__(128)
void attn_kernel(const int* __restrict__ valid_lens) {
    const int idx = blockIdx.x;
    const int q = idx & 63;
    const int h = (idx >> 6) & 7;
    const int b = idx >> 9;
    const int tid = threadIdx.x;
    const float scale = 0.125f;

    __shared__ float qs[64], qt[64], sc[64];
    __shared__ int   sidx[8];
    __shared__ float sw[8];
    __shared__ float cw[8][16];

    if (tid < 64) {
        qs[tid] = g_q_stat[(size_t)(b * 64 + q) * 512 + h * 64 + tid];
        qt[tid] = g_q_tok [(size_t)(b * 64 + q) * 512 + h * 64 + tid];
    }
    __syncthreads();

    const int vlen = valid_lens[b];

    if (tid < 64) {
        const int s = tid;
        const float* kp = &g_k_stat[(size_t)(b * 64 + s) * 512 + h * 64];
        float acc = 0.f;
#pragma unroll
        for (int d = 0; d < 64; d++) acc = fmaf(qs[d], kp[d], acc);
        sc[s] = (s < vlen) ? acc * scale : NEGV;
    }
    __syncthreads();

    if (tid == 0) {
        float tmp[64];
#pragma unroll
        for (int i = 0; i < 64; i++) tmp[i] = sc[i];
        float vals[8];
        for (int j = 0; j < 8; j++) {
            int bi = 0; float bv = tmp[0];
            for (int i = 1; i < 64; i++) {
                if (tmp[i] > bv) { bv = tmp[i]; bi = i; }
            }
            sidx[j] = bi; vals[j] = bv; tmp[bi] = -3.0e38f;
        }
        const float m = vals[0];
        float e[8], sum = 0.f;
        for (int j = 0; j < 8; j++) { e[j] = expf(vals[j] - m); sum += e[j]; }
        const float inv = 1.f / sum;
        for (int j = 0; j < 8; j++) sw[j] = e[j] * inv;
    }
    __syncthreads();

    {
        const int j = tid >> 4;
        const int t = tid & 15;
        const int s = sidx[j];
        const float* kp = &g_k_tok[(((size_t)(b * 64 + s)) * 16 + t) * 512 + h * 64];
        float acc = 0.f;
#pragma unroll
        for (int d = 0; d < 64; d++) acc = fmaf(qt[d], kp[d], acc);
        cw[j][t] = acc * scale;
    }
    __syncthreads();

    if (tid < 8) {
        const int j = tid;
        float m = cw[j][0];
#pragma unroll
        for (int t = 1; t < 16; t++) m = fmaxf(m, cw[j][t]);
        float e[16], sum = 0.f;
#pragma unroll
        for (int t = 0; t < 16; t++) { e[t] = expf(cw[j][t] - m); sum += e[t]; }
        const float f = sw[j] / sum;
#pragma unroll
        for (int t = 0; t < 16; t++) cw[j][t] = e[t] * f;
    }
    __syncthreads();

    if (tid < 64) {
        const int d = tid;
        float acc = 0.f;
#pragma unroll
        for (int j = 0; j < 8; j++) {
            const int s = sidx[j];
            const float* vp = &g_vp[(((size_t)(b * 64 + s)) * 16) * 512 + h * 64 + d];
#pragma unroll
            for (int t = 0; t < 16; t++) acc = fmaf(cw[j][t], vp[(size_t)t * 512], acc);
        }
        const size_t off = (size_t)(b * 64 + q) * 512 + h * 64 + d;
        __half hh = __float2half(acc);
        g_at_h[off] = hh;
        g_at_l[off] = __float2half(acc - __half2float(hh));
    }
}

// ---------------------------------------------------------------------------
extern "C" void kernel_launch(void* const* d_in, const int* in_sizes, int n_in,
                              void* d_out, int out_size) {
    const float* queries        = (const float*)d_in[0];
    const float* stat_keys      = (const float*)d_in[1];
    const float* token_keys     = (const float*)d_in[2];
    const float* values         = (const float*)d_in[3];
    const int*   stat_valid_len = (const int*)  d_in[4];
    WPtrs ws;
    for (int i = 0; i < 6; i++) ws.p[i] = (const float*)d_in[5 + i];
    float* out = (float*)d_out;

    // resolve device-global scratch
    __half *cq_h, *cq_l, *csk_h, *csk_l, *ctk_h, *ctk_l, *cv_h, *cv_l;
    __half *wh, *wl, *at_h, *at_l;
    float *q_stat, *q_tok, *k_stat, *k_tok, *vp;
    cudaGetSymbolAddress((void**)&cq_h,  g_cq_h);  cudaGetSymbolAddress((void**)&cq_l,  g_cq_l);
    cudaGetSymbolAddress((void**)&csk_h, g_csk_h); cudaGetSymbolAddress((void**)&csk_l, g_csk_l);
    cudaGetSymbolAddress((void**)&ctk_h, g_ctk_h); cudaGetSymbolAddress((void**)&ctk_l, g_ctk_l);
    cudaGetSymbolAddress((void**)&cv_h,  g_cv_h);  cudaGetSymbolAddress((void**)&cv_l,  g_cv_l);
    cudaGetSymbolAddress((void**)&wh,    g_wh);    cudaGetSymbolAddress((void**)&wl,    g_wl);
    cudaGetSymbolAddress((void**)&at_h,  g_at_h);  cudaGetSymbolAddress((void**)&at_l,  g_at_l);
    cudaGetSymbolAddress((void**)&q_stat, g_q_stat);
    cudaGetSymbolAddress((void**)&q_tok,  g_q_tok);
    cudaGetSymbolAddress((void**)&k_stat, g_k_stat);
    cudaGetSymbolAddress((void**)&k_tok,  g_k_tok);
    cudaGetSymbolAddress((void**)&vp,     g_vp);

    const size_t WSZ = (size_t)512 * 512;
    constexpr int SMEM_128 = 2 * (2 * 128 * 80 + 2 * 128 * 80);  // 81920
    constexpr int SMEM_64  = 2 * (2 * 64 * 80 + 2 * 128 * 80);   // 61440
    cudaFuncSetAttribute(gemm16<128, false>, cudaFuncAttributeMaxDynamicSharedMemorySize, SMEM_128);
    cudaFuncSetAttribute(gemm16<64,  false>, cudaFuncAttributeMaxDynamicSharedMemorySize, SMEM_64);
    cudaFuncSetAttribute(gemm16<64,  true >, cudaFuncAttributeMaxDynamicSharedMemorySize, SMEM_64);

    // 1) prep: weights + input conversion
    prep_w<<<dim3(16, 16, 6), dim3(32, 8)>>>(ws);
    conv_act<<<dim3(4096, 4), 256>>>(queries, stat_keys, token_keys, values);

    // 2) fused q_stat|q_tok projection: A = queries fp16, B rows [0,1024) = Wq_stat|Wq_token
    gemm16<64, true><<<dim3(8, 8), 256, SMEM_64>>>(cq_h, cq_l, wh, wl, q_stat, q_tok);
    // 3) k_stat projection
    gemm16<64, false><<<dim3(4, 8), 256, SMEM_64>>>(csk_h, csk_l, wh + 2 * WSZ, wl + 2 * WSZ, k_stat, nullptr);
    // 4) gathered token_keys / values projections (M = 8192)
    gemm16<128, false><<<dim3(4, 64), 256, SMEM_128>>>(ctk_h, ctk_l, wh + 3 * WSZ, wl + 3 * WSZ, k_tok, nullptr);
    gemm16<128, false><<<dim3(4, 64), 256, SMEM_128>>>(cv_h,  cv_l,  wh + 4 * WSZ, wl + 4 * WSZ, vp,    nullptr);

    // 5) fused hierarchical attention (emits fp16 hi/lo)
    attn_kernel<<<B_ * H_ * Q_, 128>>>(stat_valid_len);

    // 6) output projection
    gemm16<64, false><<<dim3(4, 8), 256, SMEM_64>>>(at_h, at_l, wh + 5 * WSZ, wl + 5 * WSZ, out, nullptr);
}

// round 6
// speedup vs baseline: 1.9123x; 1.0762x over previous
#include <cuda_runtime.h>
#include <cuda_fp16.h>
#include <cstdint>
#include <math.h>

#define B_   8
#define Q_   64
#define S_   64
#define T_   64
#define H_   8
#define DH_  64
#define NH_  512
#define NEGV (-1e6f)

// ---------------------------------------------------------------------------
// Scratch (device globals)
// ---------------------------------------------------------------------------
__device__ __half g_cq_h [512 * 512],  g_cq_l [512 * 512];    // queries
__device__ __half g_csk_h[512 * 512],  g_csk_l[512 * 512];    // stat_keys
__device__ __half g_ctk_h[8192 * 512], g_ctk_l[8192 * 512];   // gathered token_keys
__device__ __half g_cv_h [8192 * 512], g_cv_l [8192 * 512];   // gathered values
__device__ __half g_wh[6 * 512 * 512], g_wl[6 * 512 * 512];   // W^T [N,K] fp16 hi/lo
__device__ float g_q_stat[512 * 512];
__device__ float g_q_tok [512 * 512];
__device__ float g_k_stat[512 * 512];
__device__ float g_k_tok [8192 * 512];
__device__ float g_vp    [8192 * 512];
__device__ __half g_at_h[512 * 512], g_at_l[512 * 512];       // attn out fp16 hi/lo

// ---------------------------------------------------------------------------
// helpers
// ---------------------------------------------------------------------------
__device__ __forceinline__ uint32_t smem_u32(const void* p) {
    uint32_t a;
    asm("{ .reg .u64 t; cvta.to.shared.u64 t, %1; cvt.u32.u64 %0, t; }" : "=r"(a) : "l"(p));
    return a;
}
__device__ __forceinline__ void ldsm_x4(uint32_t* r, uint32_t addr) {
    asm volatile("ldmatrix.sync.aligned.m8n8.x4.shared.b16 {%0,%1,%2,%3}, [%4];"
        : "=r"(r[0]), "=r"(r[1]), "=r"(r[2]), "=r"(r[3]) : "r"(addr));
}
__device__ __forceinline__ void ldsm_x2(uint32_t* r, uint32_t addr) {
    asm volatile("ldmatrix.sync.aligned.m8n8.x2.shared.b16 {%0,%1}, [%2];"
        : "=r"(r[0]), "=r"(r[1]) : "r"(addr));
}
__device__ __forceinline__ void mma16816(float* d, const uint32_t* a, const uint32_t* b) {
    asm volatile("mma.sync.aligned.m16n8k16.row.col.f32.f16.f16.f32 "
        "{%0,%1,%2,%3}, {%4,%5,%6,%7}, {%8,%9}, {%0,%1,%2,%3};"
        : "+f"(d[0]), "+f"(d[1]), "+f"(d[2]), "+f"(d[3])
        : "r"(a[0]), "r"(a[1]), "r"(a[2]), "r"(a[3]), "r"(b[0]), "r"(b[1]));
}
__device__ __forceinline__ void cp16(uint32_t dst, const void* src) {
    asm volatile("cp.async.cg.shared.global [%0], [%1], 16;" :: "r"(dst), "l"(src));
}
#define CP_COMMIT() asm volatile("cp.async.commit_group;" ::: "memory")
#define CP_WAIT1()  asm volatile("cp.async.wait_group 1;" ::: "memory")
#define CP_WAIT0()  asm volatile("cp.async.wait_group 0;" ::: "memory")

// ---------------------------------------------------------------------------
// Convert inputs: fp32 -> fp16 hi/lo (token gather for z>=2)
// ---------------------------------------------------------------------------
__global__ __launch_bounds__(256)
void conv_act(const float* __restrict__ q, const float* __restrict__ sk,
              const float* __restrict__ tk, const float* __restrict__ v) {
    const int z = blockIdx.y;
    const int rows = (z < 2) ? 512 : 8192;
    const int idx = blockIdx.x * 256 + threadIdx.x;
    if (idx >= rows * 128) return;
    const int r = idx >> 7, c4 = idx & 127;
    const float* src;
    __half *dh, *dl;
    int sr = r;
    if (z == 0)      { src = q;  dh = g_cq_h;  dl = g_cq_l; }
    else if (z == 1) { src = sk; dh = g_csk_h; dl = g_csk_l; }
    else {
        sr = (r >> 4) * 64 + 48 + (r & 15);
        if (z == 2)  { src = tk; dh = g_ctk_h; dl = g_ctk_l; }
        else         { src = v;  dh = g_cv_h;  dl = g_cv_l; }
    }
    float4 x = *(const float4*)&src[(size_t)sr * 512 + c4 * 4];
    __half h0 = __float2half(x.x), h1 = __float2half(x.y),
           h2 = __float2half(x.z), h3 = __float2half(x.w);
    __half l0 = __float2half(x.x - __half2float(h0)),
           l1 = __float2half(x.y - __half2float(h1)),
           l2 = __float2half(x.z - __half2float(h2)),
           l3 = __float2half(x.w - __half2float(h3));
    uint2 hh, ll;
    hh.x = (uint32_t)__half_as_ushort(h0) | ((uint32_t)__half_as_ushort(h1) << 16);
    hh.y = (uint32_t)__half_as_ushort(h2) | ((uint32_t)__half_as_ushort(h3) << 16);
    ll.x = (uint32_t)__half_as_ushort(l0) | ((uint32_t)__half_as_ushort(l1) << 16);
    ll.y = (uint32_t)__half_as_ushort(l2) | ((uint32_t)__half_as_ushort(l3) << 16);
    *(uint2*)&dh[(size_t)r * 512 + c4 * 4] = hh;
    *(uint2*)&dl[(size_t)r * 512 + c4 * 4] = ll;
}

// ---------------------------------------------------------------------------
// Weight prep: transpose W[K,N] fp32 -> Wt[N,K] fp16 hi/lo (6 weights)
// ---------------------------------------------------------------------------
struct WPtrs { const float* p[6]; };

__global__ __launch_bounds__(256)
void prep_w(WPtrs ws) {
    __shared__ float t[32][33];
    const int widx = blockIdx.z;
    const float* W = ws.p[widx];
    __half* hiw = g_wh + (size_t)widx * 512 * 512;
    __half* low = g_wl + (size_t)widx * 512 * 512;
    const int n0 = blockIdx.x * 32, k0 = blockIdx.y * 32;
    const int tx = threadIdx.x, ty = threadIdx.y;
#pragma unroll
    for (int i = ty; i < 32; i += 8)
        t[i][tx] = W[(size_t)(k0 + i) * 512 + n0 + tx];
    __syncthreads();
#pragma unroll
    for (int i = ty; i < 32; i += 8) {
        float v = t[tx][i];
        __half h = __float2half(v);
        hiw[(size_t)(n0 + i) * 512 + k0 + tx] = h;
        low[(size_t)(n0 + i) * 512 + k0 + tx] = __float2half(v - __half2float(h));
    }
}

// ---------------------------------------------------------------------------
// Batched fp16 3-term hi/lo GEMM, cp.async 2-stage pipeline.
// Uniform 128x128 CTA tiles; up to 4 segments selected by flattened block id.
// Segment 0 may SPLIT output columns [0,512)->C0, [512,1024)->C1.
// ---------------------------------------------------------------------------
struct GemmBatch {
    const __half *Ah[4], *Al[4], *Bh[4], *Bl[4];
    float *C0[4], *C1[4];
    int nbx[4];   // CTA columns per segment
    int cnt[4];   // CTA count per segment
};

__global__ __launch_bounds__(256)
void gemm_batched(GemmBatch args) {
    constexpr int MT = 4;                       // 128/32
    constexpr uint32_t ABYTES = 128 * 80;
    constexpr uint32_t BBYTES = 128 * 80;
    constexpr uint32_t STG    = 2 * ABYTES + 2 * BBYTES;   // 40960
    extern __shared__ char smem[];
    const uint32_t sb = smem_u32(smem);

    // segment resolve
    int id = blockIdx.x, s = 0;
#pragma unroll
    for (int i = 0; i < 3; i++) {
        bool adv = (id >= args.cnt[s]);
        if (adv) { id -= args.cnt[s]; s++; }
    }
    const __half* Ah = args.Ah[s];
    const __half* Al = args.Al[s];
    const __half* Bh = args.Bh[s];
    const __half* Bl = args.Bl[s];
    float* C0 = args.C0[s];
    float* C1 = args.C1[s];
    const int nbx = args.nbx[s];
    const int bx = id % nbx, by = id / nbx;
    const int m0 = by * 128, n0 = bx * 128;

    const int tid = threadIdx.x;
    const int wid = tid >> 5, lane = tid & 31;
    const int wm = wid >> 2, wn = wid & 3;

    const uint32_t rowA = (uint32_t)(wm * 64 + (lane & 7) + ((lane >> 3) & 1) * 8);
    const uint32_t colA = (uint32_t)(((lane >> 4) & 1) * 16);
    const uint32_t oAh = rowA * 80 + colA;
    const uint32_t oAl = oAh + ABYTES;
    const uint32_t rowB = (uint32_t)(wn * 32 + (lane & 7));
    const uint32_t colB = (uint32_t)(((lane >> 3) & 1) * 16);
    const uint32_t oBh = 2 * ABYTES + rowB * 80 + colB;
    const uint32_t oBl = oBh + BBYTES;

    float acc[MT][4][4];
#pragma unroll
    for (int i = 0; i < MT; i++)
#pragma unroll
        for (int j = 0; j < 4; j++)
#pragma unroll
            for (int e = 0; e < 4; e++) acc[i][j][e] = 0.f;

    auto load_stage = [&](int st, int kc) {
        const int k0 = kc * 32;
        const uint32_t base = sb + st * STG;
#pragma unroll
        for (int i = 0; i < 2; i++) {
            int c = tid + i * 256;
            int r = c >> 2, qq = c & 3;
            uint32_t dst = base + r * 80 + qq * 16;
            const size_t ga = (size_t)(m0 + r) * 512 + k0 + qq * 8;
            cp16(dst, Ah + ga);
            cp16(dst + ABYTES, Al + ga);
            uint32_t dstB = base + 2 * ABYTES + r * 80 + qq * 16;
            const size_t gb = (size_t)(n0 + r) * 512 + k0 + qq * 8;
            cp16(dstB, Bh + gb);
            cp16(dstB + BBYTES, Bl + gb);
        }
    };

    load_stage(0, 0); CP_COMMIT();
    load_stage(1, 1); CP_COMMIT();

    for (int kc = 0; kc < 16; kc++) {
        if (kc < 15) { CP_WAIT1(); } else { CP_WAIT0(); }
        __syncthreads();
        const uint32_t so = sb + (kc & 1) * STG;
#pragma unroll
        for (int ks = 0; ks < 2; ks++) {
            uint32_t bh[4][2], bl[4][2];
#pragma unroll
            for (int ni = 0; ni < 4; ni++) ldsm_x2(bh[ni], so + oBh + ni * 640 + ks * 32);
#pragma unroll
            for (int ni = 0; ni < 4; ni++) ldsm_x2(bl[ni], so + oBl + ni * 640 + ks * 32);
#pragma unroll
            for (int mi = 0; mi < MT; mi++) {
                uint32_t ah[4], al[4];
                ldsm_x4(ah, so + oAh + mi * 1280 + ks * 32);
                ldsm_x4(al, so + oAl + mi * 1280 + ks * 32);
#pragma unroll
                for (int ni = 0; ni < 4; ni++) mma16816(acc[mi][ni], ah, bh[ni]);
#pragma unroll
                for (int ni = 0; ni < 4; ni++) mma16816(acc[mi][ni], ah, bl[ni]);
#pragma unroll
                for (int ni = 0; ni < 4; ni++) mma16816(acc[mi][ni], al, bh[ni]);
            }
        }
        __syncthreads();
        if (kc + 2 < 16) { load_stage(kc & 1, kc + 2); }
        CP_COMMIT();
    }

    // epilogue
    const int mrow = m0 + wm * 64 + (lane >> 2);
    const int ncol = n0 + wn * 32 + (lane & 3) * 2;
#pragma unroll
    for (int mi = 0; mi < MT; mi++) {
#pragma unroll
        for (int ni = 0; ni < 4; ni++) {
            int col = ncol + ni * 8;
            float* dst = (C1 && col >= 512) ? (C1 + col - 512) : (C0 + col);
            int r0 = mrow + mi * 16;
            *(float2*)&dst[(size_t)r0 * 512]       = make_float2(acc[mi][ni][0], acc[mi][ni][1]);
            *(float2*)&dst[(size_t)(r0 + 8) * 512] = make_float2(acc[mi][ni][2], acc[mi][ni][3]);
        }
    }
}

// ---------------------------------------------------------------------------
// Fused hierarchical attention; emits fp16 hi/lo for the Wo GEMM.
// ---------------------------------------------------------------------------
__global__ __launch_bounds__(128)
void attn_kernel(const int* __restrict__ valid_lens) {
    const int idx = blockIdx.x;
    const int q = idx & 63;
    const int h = (idx >> 6) & 7;
    const int b = idx >> 9;
    const int tid = threadIdx.x;
    const float scale = 0.125f;

    __shared__ float qs[64], qt[64], sc[64];
    __shared__ int   sidx[8];
    __shared__ float sw[8];
    __shared__ float cw[8][16];

    if (tid < 64) {
        qs[tid] = g_q_stat[(size_t)(b * 64 + q) * 512 + h * 64 + tid];
        qt[tid] = g_q_tok [(size_t)(b * 64 + q) * 512 + h * 64 + tid];
    }
    __syncthreads();

    const int vlen = valid_lens[b];

    if (tid < 64) {
        const int s = tid;
        const float* kp = &g_k_stat[(size_t)(b * 64 + s) * 512 + h * 64];
        float acc = 0.f;
#pragma unroll
        for (int d = 0; d < 64; d++) acc = fmaf(qs[d], kp[d], acc);
        sc[s] = (s < vlen) ? acc * scale : NEGV;
    }
    __syncthreads();

    if (tid == 0) {
        float tmp[64];
#pragma unroll
        for (int i = 0; i < 64; i++) tmp[i] = sc[i];
        float vals[8];
        for (int j = 0; j < 8; j++) {
            int bi = 0; float bv = tmp[0];
            for (int i = 1; i < 64; i++) {
                if (tmp[i] > bv) { bv = tmp[i]; bi = i; }
            }
            sidx[j] = bi; vals[j] = bv; tmp[bi] = -3.0e38f;
        }
        const float m = vals[0];
        float e[8], sum = 0.f;
        for (int j = 0; j < 8; j++) { e[j] = expf(vals[j] - m); sum += e[j]; }
        const float inv = 1.f / sum;
        for (int j = 0; j < 8; j++) sw[j] = e[j] * inv;
    }
    __syncthreads();

    {
        const int j = tid >> 4;
        const int t = tid & 15;
        const int s = sidx[j];
        const float* kp = &g_k_tok[(((size_t)(b * 64 + s)) * 16 + t) * 512 + h * 64];
        float acc = 0.f;
#pragma unroll
        for (int d = 0; d < 64; d++) acc = fmaf(qt[d], kp[d], acc);
        cw[j][t] = acc * scale;
    }
    __syncthreads();

    if (tid < 8) {
        const int j = tid;
        float m = cw[j][0];
#pragma unroll
        for (int t = 1; t < 16; t++) m = fmaxf(m, cw[j][t]);
        float e[16], sum = 0.f;
#pragma unroll
        for (int t = 0; t < 16; t++) { e[t] = expf(cw[j][t] - m); sum += e[t]; }
        const float f = sw[j] / sum;
#pragma unroll
        for (int t = 0; t < 16; t++) cw[j][t] = e[t] * f;
    }
    __syncthreads();

    if (tid < 64) {
        const int d = tid;
        float acc = 0.f;
#pragma unroll
        for (int j = 0; j < 8; j++) {
            const int s = sidx[j];
            const float* vp = &g_vp[(((size_t)(b * 64 + s)) * 16) * 512 + h * 64 + d];
#pragma unroll
            for (int t = 0; t < 16; t++) acc = fmaf(cw[j][t], vp[(size_t)t * 512], acc);
        }
        const size_t off = (size_t)(b * 64 + q) * 512 + h * 64 + d;
        __half hh = __float2half(acc);
        g_at_h[off] = hh;
        g_at_l[off] = __float2half(acc - __half2float(hh));
    }
}

// ---------------------------------------------------------------------------
extern "C" void kernel_launch(void* const* d_in, const int* in_sizes, int n_in,
                              void* d_out, int out_size) {
    const float* queries        = (const float*)d_in[0];
    const float* stat_keys      = (const float*)d_in[1];
    const float* token_keys     = (const float*)d_in[2];
    const float* values         = (const float*)d_in[3];
    const int*   stat_valid_len = (const int*)  d_in[4];
    WPtrs ws;
    for (int i = 0; i < 6; i++) ws.p[i] = (const float*)d_in[5 + i];
    float* out = (float*)d_out;

    __half *cq_h, *cq_l, *csk_h, *csk_l, *ctk_h, *ctk_l, *cv_h, *cv_l;
    __half *wh, *wl, *at_h, *at_l;
    float *q_stat, *q_tok, *k_stat, *k_tok, *vp;
    cudaGetSymbolAddress((void**)&cq_h,  g_cq_h);  cudaGetSymbolAddress((void**)&cq_l,  g_cq_l);
    cudaGetSymbolAddress((void**)&csk_h, g_csk_h); cudaGetSymbolAddress((void**)&csk_l, g_csk_l);
    cudaGetSymbolAddress((void**)&ctk_h, g_ctk_h); cudaGetSymbolAddress((void**)&ctk_l, g_ctk_l);
    cudaGetSymbolAddress((void**)&cv_h,  g_cv_h);  cudaGetSymbolAddress((void**)&cv_l,  g_cv_l);
    cudaGetSymbolAddress((void**)&wh,    g_wh);    cudaGetSymbolAddress((void**)&wl,    g_wl);
    cudaGetSymbolAddress((void**)&at_h,  g_at_h);  cudaGetSymbolAddress((void**)&at_l,  g_at_l);
    cudaGetSymbolAddress((void**)&q_stat, g_q_stat);
    cudaGetSymbolAddress((void**)&q_tok,  g_q_tok);
    cudaGetSymbolAddress((void**)&k_stat, g_k_stat);
    cudaGetSymbolAddress((void**)&k_tok,  g_k_tok);
    cudaGetSymbolAddress((void**)&vp,     g_vp);

    const size_t WSZ = (size_t)512 * 512;
    constexpr int SMEM = 2 * (2 * 128 * 80 + 2 * 128 * 80);  // 81920
    cudaFuncSetAttribute(gemm_batched, cudaFuncAttributeMaxDynamicSharedMemorySize, SMEM);

    // 1) prep: weights + input conversion
    prep_w<<<dim3(16, 16, 6), dim3(32, 8)>>>(ws);
    conv_act<<<dim3(4096, 4), 256>>>(queries, stat_keys, token_keys, values);

    // 2) all five projections in ONE launch (560 CTAs)
    GemmBatch gb;
    // seg 0: queries @ [Wq_stat|Wq_token]  (M=512, N=1024, split)
    gb.Ah[0] = cq_h;  gb.Al[0] = cq_l;  gb.Bh[0] = wh;           gb.Bl[0] = wl;
    gb.C0[0] = q_stat; gb.C1[0] = q_tok; gb.nbx[0] = 8; gb.cnt[0] = 32;
    // seg 1: stat_keys @ Wk_stat           (M=512, N=512)
    gb.Ah[1] = csk_h; gb.Al[1] = csk_l; gb.Bh[1] = wh + 2 * WSZ; gb.Bl[1] = wl + 2 * WSZ;
    gb.C0[1] = k_stat; gb.C1[1] = nullptr; gb.nbx[1] = 4; gb.cnt[1] = 16;
    // seg 2: token_keys16 @ Wk_token       (M=8192, N=512)
    gb.Ah[2] = ctk_h; gb.Al[2] = ctk_l; gb.Bh[2] = wh + 3 * WSZ; gb.Bl[2] = wl + 3 * WSZ;
    gb.C0[2] = k_tok; gb.C1[2] = nullptr; gb.nbx[2] = 4; gb.cnt[2] = 256;
    // seg 3: values16 @ Wv                 (M=8192, N=512)
    gb.Ah[3] = cv_h;  gb.Al[3] = cv_l;  gb.Bh[3] = wh + 4 * WSZ; gb.Bl[3] = wl + 4 * WSZ;
    gb.C0[3] = vp;    gb.C1[3] = nullptr; gb.nbx[3] = 4; gb.cnt[3] = 256;
    gemm_batched<<<560, 256, SMEM>>>(gb);

    // 3) fused hierarchical attention
    attn_kernel<<<B_ * H_ * Q_, 128>>>(stat_valid_len);

    // 4) output projection (single-segment batch)
    GemmBatch go;
    go.Ah[0] = at_h; go.Al[0] = at_l; go.Bh[0] = wh + 5 * WSZ; go.Bl[0] = wl + 5 * WSZ;
    go.C0[0] = out;  go.C1[0] = nullptr; go.nbx[0] = 4; go.cnt[0] = 16;
    go.cnt[1] = go.cnt[2] = go.cnt[3] = 0x7fffffff;
    go.Ah[1] = go.Ah[2] = go.Ah[3] = at_h; go.Al[1] = go.Al[2] = go.Al[3] = at_l;
    go.Bh[1] = go.Bh[2] = go.Bh[3] = wh;   go.Bl[1] = go.Bl[2] = go.Bl[3] = wl;
    go.C0[1] = go.C0[2] = go.C0[3] = out;  go.C1[1] = go.C1[2] = go.C1[3] = nullptr;
    go.nbx[1] = go.nbx[2] = go.nbx[3] = 4;
    gemm_batched<<<16, 256, SMEM>>>(go);
}

// round 7
// speedup vs baseline: 3.3198x; 1.7361x over previous
#include <cuda_runtime.h>
#include <cuda_fp16.h>
#include <cstdint>
#include <math.h>

#define B_   8
#define Q_   64
#define S_   64
#define T_   64
#define H_   8
#define DH_  64
#define NH_  512
#define NEGV (-1e6f)

// ---------------------------------------------------------------------------
// Scratch (device globals)
// ---------------------------------------------------------------------------
__device__ __half g_cq_h [512 * 512],  g_cq_l [512 * 512];    // queries
__device__ __half g_csk_h[512 * 512],  g_csk_l[512 * 512];    // stat_keys
__device__ __half g_ctk_h[8192 * 512], g_ctk_l[8192 * 512];   // gathered token_keys
__device__ __half g_cv_h [8192 * 512], g_cv_l [8192 * 512];   // gathered values
__device__ __half g_wh[6 * 512 * 512], g_wl[6 * 512 * 512];   // W^T [N,K] fp16 hi/lo
__device__ float g_q_stat[512 * 512];
__device__ float g_q_tok [512 * 512];
__device__ float g_k_stat[512 * 512];
__device__ float g_k_tok [8192 * 512];
__device__ float g_vp    [8192 * 512];
__device__ __half g_at_h[512 * 512], g_at_l[512 * 512];       // attn out fp16 hi/lo

// ---------------------------------------------------------------------------
// helpers
// ---------------------------------------------------------------------------
__device__ __forceinline__ uint32_t smem_u32(const void* p) {
    uint32_t a;
    asm("{ .reg .u64 t; cvta.to.shared.u64 t, %1; cvt.u32.u64 %0, t; }" : "=r"(a) : "l"(p));
    return a;
}
__device__ __forceinline__ void ldsm_x4(uint32_t* r, uint32_t addr) {
    asm volatile("ldmatrix.sync.aligned.m8n8.x4.shared.b16 {%0,%1,%2,%3}, [%4];"
        : "=r"(r[0]), "=r"(r[1]), "=r"(r[2]), "=r"(r[3]) : "r"(addr));
}
__device__ __forceinline__ void ldsm_x2(uint32_t* r, uint32_t addr) {
    asm volatile("ldmatrix.sync.aligned.m8n8.x2.shared.b16 {%0,%1}, [%2];"
        : "=r"(r[0]), "=r"(r[1]) : "r"(addr));
}
__device__ __forceinline__ void mma16816(float* d, const uint32_t* a, const uint32_t* b) {
    asm volatile("mma.sync.aligned.m16n8k16.row.col.f32.f16.f16.f32 "
        "{%0,%1,%2,%3}, {%4,%5,%6,%7}, {%8,%9}, {%0,%1,%2,%3};"
        : "+f"(d[0]), "+f"(d[1]), "+f"(d[2]), "+f"(d[3])
        : "r"(a[0]), "r"(a[1]), "r"(a[2]), "r"(a[3]), "r"(b[0]), "r"(b[1]));
}
__device__ __forceinline__ void cp16(uint32_t dst, const void* src) {
    asm volatile("cp.async.cg.shared.global [%0], [%1], 16;" :: "r"(dst), "l"(src));
}
#define CP_COMMIT() asm volatile("cp.async.commit_group;" ::: "memory")
#define CP_WAIT1()  asm volatile("cp.async.wait_group 1;" ::: "memory")
#define CP_WAIT0()  asm volatile("cp.async.wait_group 0;" ::: "memory")

// ---------------------------------------------------------------------------
// Convert inputs: fp32 -> fp16 hi/lo (token gather for z>=2)
// ---------------------------------------------------------------------------
__global__ __launch_bounds__(256)
void conv_act(const float* __restrict__ q, const float* __restrict__ sk,
              const float* __restrict__ tk, const float* __restrict__ v) {
    const int z = blockIdx.y;
    const int rows = (z < 2) ? 512 : 8192;
    const int idx = blockIdx.x * 256 + threadIdx.x;
    if (idx >= rows * 128) return;
    const int r = idx >> 7, c4 = idx & 127;
    const float* src;
    __half *dh, *dl;
    int sr = r;
    if (z == 0)      { src = q;  dh = g_cq_h;  dl = g_cq_l; }
    else if (z == 1) { src = sk; dh = g_csk_h; dl = g_csk_l; }
    else {
        sr = (r >> 4) * 64 + 48 + (r & 15);
        if (z == 2)  { src = tk; dh = g_ctk_h; dl = g_ctk_l; }
        else         { src = v;  dh = g_cv_h;  dl = g_cv_l; }
    }
    float4 x = *(const float4*)&src[(size_t)sr * 512 + c4 * 4];
    __half h0 = __float2half(x.x), h1 = __float2half(x.y),
           h2 = __float2half(x.z), h3 = __float2half(x.w);
    __half l0 = __float2half(x.x - __half2float(h0)),
           l1 = __float2half(x.y - __half2float(h1)),
           l2 = __float2half(x.z - __half2float(h2)),
           l3 = __float2half(x.w - __half2float(h3));
    uint2 hh, ll;
    hh.x = (uint32_t)__half_as_ushort(h0) | ((uint32_t)__half_as_ushort(h1) << 16);
    hh.y = (uint32_t)__half_as_ushort(h2) | ((uint32_t)__half_as_ushort(h3) << 16);
    ll.x = (uint32_t)__half_as_ushort(l0) | ((uint32_t)__half_as_ushort(l1) << 16);
    ll.y = (uint32_t)__half_as_ushort(l2) | ((uint32_t)__half_as_ushort(l3) << 16);
    *(uint2*)&dh[(size_t)r * 512 + c4 * 4] = hh;
    *(uint2*)&dl[(size_t)r * 512 + c4 * 4] = ll;
}

// ---------------------------------------------------------------------------
// Weight prep: transpose W[K,N] fp32 -> Wt[N,K] fp16 hi/lo (6 weights)
// ---------------------------------------------------------------------------
struct WPtrs { const float* p[6]; };

__global__ __launch_bounds__(256)
void prep_w(WPtrs ws) {
    __shared__ float t[32][33];
    const int widx = blockIdx.z;
    const float* W = ws.p[widx];
    __half* hiw = g_wh + (size_t)widx * 512 * 512;
    __half* low = g_wl + (size_t)widx * 512 * 512;
    const int n0 = blockIdx.x * 32, k0 = blockIdx.y * 32;
    const int tx = threadIdx.x, ty = threadIdx.y;
#pragma unroll
    for (int i = ty; i < 32; i += 8)
        t[i][tx] = W[(size_t)(k0 + i) * 512 + n0 + tx];
    __syncthreads();
#pragma unroll
    for (int i = ty; i < 32; i += 8) {
        float v = t[tx][i];
        __half h = __float2half(v);
        hiw[(size_t)(n0 + i) * 512 + k0 + tx] = h;
        low[(size_t)(n0 + i) * 512 + k0 + tx] = __float2half(v - __half2float(h));
    }
}

// ---------------------------------------------------------------------------
// Batched fp16 3-term hi/lo GEMM, cp.async 2-stage pipeline (round 6, passing)
// ---------------------------------------------------------------------------
struct GemmBatch {
    const __half *Ah[4], *Al[4], *Bh[4], *Bl[4];
    float *C0[4], *C1[4];
    int nbx[4];
    int cnt[4];
};

__global__ __launch_bounds__(256)
void gemm_batched(GemmBatch args) {
    constexpr int MT = 4;
    constexpr uint32_t ABYTES = 128 * 80;
    constexpr uint32_t BBYTES = 128 * 80;
    constexpr uint32_t STG    = 2 * ABYTES + 2 * BBYTES;
    extern __shared__ char smem[];
    const uint32_t sb = smem_u32(smem);

    int id = blockIdx.x, s = 0;
#pragma unroll
    for (int i = 0; i < 3; i++) {
        bool adv = (id >= args.cnt[s]);
        if (adv) { id -= args.cnt[s]; s++; }
    }
    const __half* Ah = args.Ah[s];
    const __half* Al = args.Al[s];
    const __half* Bh = args.Bh[s];
    const __half* Bl = args.Bl[s];
    float* C0 = args.C0[s];
    float* C1 = args.C1[s];
    const int nbx = args.nbx[s];
    const int bx = id % nbx, by = id / nbx;
    const int m0 = by * 128, n0 = bx * 128;

    const int tid = threadIdx.x;
    const int wid = tid >> 5, lane = tid & 31;
    const int wm = wid >> 2, wn = wid & 3;

    const uint32_t rowA = (uint32_t)(wm * 64 + (lane & 7) + ((lane >> 3) & 1) * 8);
    const uint32_t colA = (uint32_t)(((lane >> 4) & 1) * 16);
    const uint32_t oAh = rowA * 80 + colA;
    const uint32_t oAl = oAh + ABYTES;
    const uint32_t rowB = (uint32_t)(wn * 32 + (lane & 7));
    const uint32_t colB = (uint32_t)(((lane >> 3) & 1) * 16);
    const uint32_t oBh = 2 * ABYTES + rowB * 80 + colB;
    const uint32_t oBl = oBh + BBYTES;

    float acc[MT][4][4];
#pragma unroll
    for (int i = 0; i < MT; i++)
#pragma unroll
        for (int j = 0; j < 4; j++)
#pragma unroll
            for (int e = 0; e < 4; e++) acc[i][j][e] = 0.f;

    auto load_stage = [&](int st, int kc) {
        const int k0 = kc * 32;
        const uint32_t base = sb + st * STG;
#pragma unroll
        for (int i = 0; i < 2; i++) {
            int c = tid + i * 256;
            int r = c >> 2, qq = c & 3;
            uint32_t dst = base + r * 80 + qq * 16;
            const size_t ga = (size_t)(m0 + r) * 512 + k0 + qq * 8;
            cp16(dst, Ah + ga);
            cp16(dst + ABYTES, Al + ga);
            uint32_t dstB = base + 2 * ABYTES + r * 80 + qq * 16;
            const size_t gb = (size_t)(n0 + r) * 512 + k0 + qq * 8;
            cp16(dstB, Bh + gb);
            cp16(dstB + BBYTES, Bl + gb);
        }
    };

    load_stage(0, 0); CP_COMMIT();
    load_stage(1, 1); CP_COMMIT();

    for (int kc = 0; kc < 16; kc++) {
        if (kc < 15) { CP_WAIT1(); } else { CP_WAIT0(); }
        __syncthreads();
        const uint32_t so = sb + (kc & 1) * STG;
#pragma unroll
        for (int ks = 0; ks < 2; ks++) {
            uint32_t bh[4][2], bl[4][2];
#pragma unroll
            for (int ni = 0; ni < 4; ni++) ldsm_x2(bh[ni], so + oBh + ni * 640 + ks * 32);
#pragma unroll
            for (int ni = 0; ni < 4; ni++) ldsm_x2(bl[ni], so + oBl + ni * 640 + ks * 32);
#pragma unroll
            for (int mi = 0; mi < MT; mi++) {
                uint32_t ah[4], al[4];
                ldsm_x4(ah, so + oAh + mi * 1280 + ks * 32);
                ldsm_x4(al, so + oAl + mi * 1280 + ks * 32);
#pragma unroll
                for (int ni = 0; ni < 4; ni++) mma16816(acc[mi][ni], ah, bh[ni]);
#pragma unroll
                for (int ni = 0; ni < 4; ni++) mma16816(acc[mi][ni], ah, bl[ni]);
#pragma unroll
                for (int ni = 0; ni < 4; ni++) mma16816(acc[mi][ni], al, bh[ni]);
            }
        }
        __syncthreads();
        if (kc + 2 < 16) { load_stage(kc & 1, kc + 2); }
        CP_COMMIT();
    }

    const int mrow = m0 + wm * 64 + (lane >> 2);
    const int ncol = n0 + wn * 32 + (lane & 3) * 2;
#pragma unroll
    for (int mi = 0; mi < MT; mi++) {
#pragma unroll
        for (int ni = 0; ni < 4; ni++) {
            int col = ncol + ni * 8;
            float* dst = (C1 && col >= 512) ? (C1 + col - 512) : (C0 + col);
            int r0 = mrow + mi * 16;
            *(float2*)&dst[(size_t)r0 * 512]       = make_float2(acc[mi][ni][0], acc[mi][ni][1]);
            *(float2*)&dst[(size_t)(r0 + 8) * 512] = make_float2(acc[mi][ni][2], acc[mi][ni][3]);
        }
    }
}

// ---------------------------------------------------------------------------
// Fused hierarchical attention — fully coalesced / warp-cooperative version.
// One block per (b,h,q), 128 threads (4 warps).
// ---------------------------------------------------------------------------
__global__ __launch_bounds__(128)
void attn_kernel(const int* __restrict__ valid_lens) {
    const int idx = blockIdx.x;
    const int q = idx & 63;
    const int h = (idx >> 6) & 7;
    const int b = idx >> 9;
    const int tid = threadIdx.x, wid = tid >> 5, lane = tid & 31;
    const float scale = 0.125f;

    __shared__ float qs[64], qt[64], sc[64];
    __shared__ int   sidx[8];
    __shared__ float svals[8];
    __shared__ float sw8[8];
    __shared__ float cw[128];
    __shared__ float pv[2][64];

    if (tid < 64) {
        qs[tid] = g_q_stat[(size_t)(b * 64 + q) * 512 + h * 64 + tid];
        qt[tid] = g_q_tok [(size_t)(b * 64 + q) * 512 + h * 64 + tid];
    }
    __syncthreads();

    const int vlen = valid_lens[b];

    // --- Phase A: stat scores; warp-cooperative dots, coalesced loads ---
    {
        const float q0 = qs[lane], q1 = qs[lane + 32];
#pragma unroll
        for (int i = 0; i < 16; i++) {
            const int s = wid * 16 + i;
            const float* kp = &g_k_stat[(size_t)(b * 64 + s) * 512 + h * 64];
            float part = q0 * kp[lane] + q1 * kp[lane + 32];
#pragma unroll
            for (int o = 16; o; o >>= 1) part += __shfl_xor_sync(~0u, part, o);
            if (lane == 0) sc[s] = (s < vlen) ? part * scale : NEGV;
        }
    }
    __syncthreads();

    // --- Phase B: top-8 via warp-parallel argmax (warp 0); first-max tiebreak ---
    if (wid == 0) {
        float v0 = sc[lane], v1 = sc[lane + 32];
        int i0 = lane, i1 = lane + 32;
#pragma unroll
        for (int j = 0; j < 8; j++) {
            float m; int mi;
            if (v0 >= v1) { m = v0; mi = i0; } else { m = v1; mi = i1; }
#pragma unroll
            for (int o = 16; o; o >>= 1) {
                float om = __shfl_xor_sync(~0u, m, o);
                int   oi = __shfl_xor_sync(~0u, mi, o);
                if (om > m || (om == m && oi < mi)) { m = om; mi = oi; }
            }
            if (lane == 0) { sidx[j] = mi; svals[j] = m; }
            if (i0 == mi) v0 = -3.0e38f;
            if (i1 == mi) v1 = -3.0e38f;
        }
        if (lane == 0) {
            const float m = svals[0];
            float e[8], sum = 0.f;
#pragma unroll
            for (int j = 0; j < 8; j++) { e[j] = expf(svals[j] - m); sum += e[j]; }
            const float inv = 1.f / sum;
#pragma unroll
            for (int j = 0; j < 8; j++) sw8[j] = e[j] * inv;
        }
    }
    __syncthreads();

    // --- Phase C: token scores; warp-cooperative dots, coalesced loads ---
    {
        const float q0 = qt[lane], q1 = qt[lane + 32];
#pragma unroll
        for (int i = 0; i < 32; i++) {
            const int p = wid * 32 + i;
            const int j = p >> 4, t = p & 15;
            const int s = sidx[j];
            const float* kp = &g_k_tok[(((size_t)(b * 64 + s)) * 16 + t) * 512 + h * 64];
            float part = q0 * kp[lane] + q1 * kp[lane + 32];
#pragma unroll
            for (int o = 16; o; o >>= 1) part += __shfl_xor_sync(~0u, part, o);
            if (lane == 0) cw[p] = part * scale;
        }
    }
    __syncthreads();

    // --- Phase D: per-segment token softmax fused with stat weight ---
    if (tid < 8) {
        const int j = tid;
        float m = cw[j * 16];
#pragma unroll
        for (int t = 1; t < 16; t++) m = fmaxf(m, cw[j * 16 + t]);
        float e[16], sum = 0.f;
#pragma unroll
        for (int t = 0; t < 16; t++) { e[t] = expf(cw[j * 16 + t] - m); sum += e[t]; }
        const float f = sw8[j] / sum;
#pragma unroll
        for (int t = 0; t < 16; t++) cw[j * 16 + t] = e[t] * f;
    }
    __syncthreads();

    // --- Phase E: weighted V reduction; j split across two halves ---
    {
        const int half = tid >> 6, d = tid & 63;
        float acc = 0.f;
#pragma unroll
        for (int jj = 0; jj < 4; jj++) {
            const int j = half * 4 + jj;
            const int s = sidx[j];
            const float* vp = &g_vp[(((size_t)(b * 64 + s)) * 16) * 512 + h * 64 + d];
#pragma unroll
            for (int t = 0; t < 16; t++) acc = fmaf(cw[j * 16 + t], vp[(size_t)t * 512], acc);
        }
        pv[half][d] = acc;
    }
    __syncthreads();

    if (tid < 64) {
        const float r = pv[0][tid] + pv[1][tid];
        const size_t off = (size_t)(b * 64 + q) * 512 + h * 64 + tid;
        __half hh = __float2half(r);
        g_at_h[off] = hh;
        g_at_l[off] = __float2half(r - __half2float(hh));
    }
}

// ---------------------------------------------------------------------------
extern "C" void kernel_launch(void* const* d_in, const int* in_sizes, int n_in,
                              void* d_out, int out_size) {
    const float* queries        = (const float*)d_in[0];
    const float* stat_keys      = (const float*)d_in[1];
    const float* token_keys     = (const float*)d_in[2];
    const float* values         = (const float*)d_in[3];
    const int*   stat_valid_len = (const int*)  d_in[4];
    WPtrs ws;
    for (int i = 0; i < 6; i++) ws.p[i] = (const float*)d_in[5 + i];
    float* out = (float*)d_out;

    __half *cq_h, *cq_l, *csk_h, *csk_l, *ctk_h, *ctk_l, *cv_h, *cv_l;
    __half *wh, *wl, *at_h, *at_l;
    float *q_stat, *q_tok, *k_stat, *k_tok, *vp;
    cudaGetSymbolAddress((void**)&cq_h,  g_cq_h);  cudaGetSymbolAddress((void**)&cq_l,  g_cq_l);
    cudaGetSymbolAddress((void**)&csk_h, g_csk_h); cudaGetSymbolAddress((void**)&csk_l, g_csk_l);
    cudaGetSymbolAddress((void**)&ctk_h, g_ctk_h); cudaGetSymbolAddress((void**)&ctk_l, g_ctk_l);
    cudaGetSymbolAddress((void**)&cv_h,  g_cv_h);  cudaGetSymbolAddress((void**)&cv_l,  g_cv_l);
    cudaGetSymbolAddress((void**)&wh,    g_wh);    cudaGetSymbolAddress((void**)&wl,    g_wl);
    cudaGetSymbolAddress((void**)&at_h,  g_at_h);  cudaGetSymbolAddress((void**)&at_l,  g_at_l);
    cudaGetSymbolAddress((void**)&q_stat, g_q_stat);
    cudaGetSymbolAddress((void**)&q_tok,  g_q_tok);
    cudaGetSymbolAddress((void**)&k_stat, g_k_stat);
    cudaGetSymbolAddress((void**)&k_tok,  g_k_tok);
    cudaGetSymbolAddress((void**)&vp,     g_vp);

    const size_t WSZ = (size_t)512 * 512;
    constexpr int SMEM = 2 * (2 * 128 * 80 + 2 * 128 * 80);  // 81920
    cudaFuncSetAttribute(gemm_batched, cudaFuncAttributeMaxDynamicSharedMemorySize, SMEM);

    // 1) prep
    prep_w<<<dim3(16, 16, 6), dim3(32, 8)>>>(ws);
    conv_act<<<dim3(4096, 4), 256>>>(queries, stat_keys, token_keys, values);

    // 2) all five projections in one launch (560 CTAs)
    GemmBatch gb;
    gb.Ah[0] = cq_h;  gb.Al[0] = cq_l;  gb.Bh[0] = wh;           gb.Bl[0] = wl;
    gb.C0[0] = q_stat; gb.C1[0] = q_tok; gb.nbx[0] = 8; gb.cnt[0] = 32;
    gb.Ah[1] = csk_h; gb.Al[1] = csk_l; gb.Bh[1] = wh + 2 * WSZ; gb.Bl[1] = wl + 2 * WSZ;
    gb.C0[1] = k_stat; gb.C1[1] = nullptr; gb.nbx[1] = 4; gb.cnt[1] = 16;
    gb.Ah[2] = ctk_h; gb.Al[2] = ctk_l; gb.Bh[2] = wh + 3 * WSZ; gb.Bl[2] = wl + 3 * WSZ;
    gb.C0[2] = k_tok; gb.C1[2] = nullptr; gb.nbx[2] = 4; gb.cnt[2] = 256;
    gb.Ah[3] = cv_h;  gb.Al[3] = cv_l;  gb.Bh[3] = wh + 4 * WSZ; gb.Bl[3] = wl + 4 * WSZ;
    gb.C0[3] = vp;    gb.C1[3] = nullptr; gb.nbx[3] = 4; gb.cnt[3] = 256;
    gemm_batched<<<560, 256, SMEM>>>(gb);

    // 3) fused hierarchical attention (coalesced)
    attn_kernel<<<B_ * H_ * Q_, 128>>>(stat_valid_len);

    // 4) output projection
    GemmBatch go;
    go.Ah[0] = at_h; go.Al[0] = at_l; go.Bh[0] = wh + 5 * WSZ; go.Bl[0] = wl + 5 * WSZ;
    go.C0[0] = out;  go.C1[0] = nullptr; go.nbx[0] = 4; go.cnt[0] = 16;
    go.cnt[1] = go.cnt[2] = go.cnt[3] = 0x7fffffff;
    go.Ah[1] = go.Ah[2] = go.Ah[3] = at_h; go.Al[1] = go.Al[2] = go.Al[3] = at_l;
    go.Bh[1] = go.Bh[2] = go.Bh[3] = wh;   go.Bl[1] = go.Bl[2] = go.Bl[3] = wl;
    go.C0[1] = go.C0[2] = go.C0[3] = out;  go.C1[1] = go.C1[2] = go.C1[3] = nullptr;
    go.nbx[1] = go.nbx[2] = go.nbx[3] = 4;
    gemm_batched<<<16, 256, SMEM>>>(go);
}

// round 8
// speedup vs baseline: 3.6701x; 1.1055x over previous
#include <cuda_runtime.h>
#include <cuda_fp16.h>
#include <cstdint>
#include <math.h>

#define B_   8
#define Q_   64
#define S_   64
#define T_   64
#define H_   8
#define DH_  64
#define NH_  512
#define NEGV (-1e6f)

// ---------------------------------------------------------------------------
// Scratch (device globals)
// ---------------------------------------------------------------------------
__device__ __half g_cq_h [512 * 512],  g_cq_l [512 * 512];    // queries hi/lo
__device__ __half g_csk_h[512 * 512],  g_csk_l[512 * 512];    // stat_keys hi/lo
__device__ __half g_ctk_h[8192 * 512];                        // gathered token_keys (hi only)
__device__ __half g_cv_h [8192 * 512];                        // gathered values (hi only)
__device__ __half g_wh[6 * 512 * 512], g_wl[6 * 512 * 512];   // W^T [N,K] fp16 hi/lo
__device__ float g_q_stat[512 * 512];
__device__ float g_q_tok [512 * 512];
__device__ float g_k_stat[512 * 512];
__device__ __half g_ktk16[8192 * 512];                        // projected token keys (fp16)
__device__ __half g_v16h [8192 * 512];                        // projected values (fp16)
__device__ __half g_at_h[512 * 512], g_at_l[512 * 512];       // attn out fp16 hi/lo

// ---------------------------------------------------------------------------
// helpers
// ---------------------------------------------------------------------------
__device__ __forceinline__ uint32_t smem_u32(const void* p) {
    uint32_t a;
    asm("{ .reg .u64 t; cvta.to.shared.u64 t, %1; cvt.u32.u64 %0, t; }" : "=r"(a) : "l"(p));
    return a;
}
__device__ __forceinline__ void ldsm_x4(uint32_t* r, uint32_t addr) {
    asm volatile("ldmatrix.sync.aligned.m8n8.x4.shared.b16 {%0,%1,%2,%3}, [%4];"
        : "=r"(r[0]), "=r"(r[1]), "=r"(r[2]), "=r"(r[3]) : "r"(addr));
}
__device__ __forceinline__ void ldsm_x2(uint32_t* r, uint32_t addr) {
    asm volatile("ldmatrix.sync.aligned.m8n8.x2.shared.b16 {%0,%1}, [%2];"
        : "=r"(r[0]), "=r"(r[1]) : "r"(addr));
}
__device__ __forceinline__ void mma16816(float* d, const uint32_t* a, const uint32_t* b) {
    asm volatile("mma.sync.aligned.m16n8k16.row.col.f32.f16.f16.f32 "
        "{%0,%1,%2,%3}, {%4,%5,%6,%7}, {%8,%9}, {%0,%1,%2,%3};"
        : "+f"(d[0]), "+f"(d[1]), "+f"(d[2]), "+f"(d[3])
        : "r"(a[0]), "r"(a[1]), "r"(a[2]), "r"(a[3]), "r"(b[0]), "r"(b[1]));
}
__device__ __forceinline__ void cp16(uint32_t dst, const void* src) {
    asm volatile("cp.async.cg.shared.global [%0], [%1], 16;" :: "r"(dst), "l"(src));
}
#define CP_COMMIT() asm volatile("cp.async.commit_group;" ::: "memory")
#define CP_WAIT1()  asm volatile("cp.async.wait_group 1;" ::: "memory")
#define CP_WAIT0()  asm volatile("cp.async.wait_group 0;" ::: "memory")

// ---------------------------------------------------------------------------
// Convert inputs: q/sk -> fp16 hi/lo; gathered tk/v -> fp16 hi only
// ---------------------------------------------------------------------------
__global__ __launch_bounds__(256)
void conv_act(const float* __restrict__ q, const float* __restrict__ sk,
              const float* __restrict__ tk, const float* __restrict__ v) {
    const int z = blockIdx.y;
    const int rows = (z < 2) ? 512 : 8192;
    const int idx = blockIdx.x * 256 + threadIdx.x;
    if (idx >= rows * 128) return;
    const int r = idx >> 7, c4 = idx & 127;

    if (z < 2) {
        const float* src = z ? sk : q;
        __half* dh = z ? g_csk_h : g_cq_h;
        __half* dl = z ? g_csk_l : g_cq_l;
        float4 x = *(const float4*)&src[(size_t)r * 512 + c4 * 4];
        __half h0 = __float2half(x.x), h1 = __float2half(x.y),
               h2 = __float2half(x.z), h3 = __float2half(x.w);
        __half l0 = __float2half(x.x - __half2float(h0)),
               l1 = __float2half(x.y - __half2float(h1)),
               l2 = __float2half(x.z - __half2float(h2)),
               l3 = __float2half(x.w - __half2float(h3));
        uint2 hh, ll;
        hh.x = (uint32_t)__half_as_ushort(h0) | ((uint32_t)__half_as_ushort(h1) << 16);
        hh.y = (uint32_t)__half_as_ushort(h2) | ((uint32_t)__half_as_ushort(h3) << 16);
        ll.x = (uint32_t)__half_as_ushort(l0) | ((uint32_t)__half_as_ushort(l1) << 16);
        ll.y = (uint32_t)__half_as_ushort(l2) | ((uint32_t)__half_as_ushort(l3) << 16);
        *(uint2*)&dh[(size_t)r * 512 + c4 * 4] = hh;
        *(uint2*)&dl[(size_t)r * 512 + c4 * 4] = ll;
    } else {
        const int sr = (r >> 4) * 64 + 48 + (r & 15);
        const float* src = (z == 2) ? tk : v;
        __half* dh = (z == 2) ? g_ctk_h : g_cv_h;
        float4 x = *(const float4*)&src[(size_t)sr * 512 + c4 * 4];
        uint2 hh;
        hh.x = (uint32_t)__half_as_ushort(__float2half(x.x)) |
               ((uint32_t)__half_as_ushort(__float2half(x.y)) << 16);
        hh.y = (uint32_t)__half_as_ushort(__float2half(x.z)) |
               ((uint32_t)__half_as_ushort(__float2half(x.w)) << 16);
        *(uint2*)&dh[(size_t)r * 512 + c4 * 4] = hh;
    }
}

// ---------------------------------------------------------------------------
// Weight prep: transpose W[K,N] fp32 -> Wt[N,K] fp16 hi/lo (6 weights)
// ---------------------------------------------------------------------------
struct WPtrs { const float* p[6]; };

__global__ __launch_bounds__(256)
void prep_w(WPtrs ws) {
    __shared__ float t[32][33];
    const int widx = blockIdx.z;
    const float* W = ws.p[widx];
    __half* hiw = g_wh + (size_t)widx * 512 * 512;
    __half* low = g_wl + (size_t)widx * 512 * 512;
    const int n0 = blockIdx.x * 32, k0 = blockIdx.y * 32;
    const int tx = threadIdx.x, ty = threadIdx.y;
#pragma unroll
    for (int i = ty; i < 32; i += 8)
        t[i][tx] = W[(size_t)(k0 + i) * 512 + n0 + tx];
    __syncthreads();
#pragma unroll
    for (int i = ty; i < 32; i += 8) {
        float v = t[tx][i];
        __half h = __float2half(v);
        hiw[(size_t)(n0 + i) * 512 + k0 + tx] = h;
        low[(size_t)(n0 + i) * 512 + k0 + tx] = __float2half(v - __half2float(h));
    }
}

// ---------------------------------------------------------------------------
// Batched fp16 hi/lo GEMM, cp.async 2-stage pipeline.
// Per segment: Al != nullptr -> 3-term (AhBh + AhBl + AlBh); else 2-term.
// Ho != nullptr -> write __half output; else fp32 (C0/C1 split).
// ---------------------------------------------------------------------------
struct GemmBatch {
    const __half *Ah[4], *Al[4], *Bh[4], *Bl[4];
    float *C0[4], *C1[4];
    __half *Ho[4];
    int nbx[4];
    int cnt[4];
};

__global__ __launch_bounds__(256)
void gemm_batched(GemmBatch args) {
    constexpr int MT = 4;
    constexpr uint32_t ABYTES = 128 * 80;
    constexpr uint32_t BBYTES = 128 * 80;
    constexpr uint32_t STG    = 2 * ABYTES + 2 * BBYTES;
    extern __shared__ char smem[];
    const uint32_t sb = smem_u32(smem);

    int id = blockIdx.x, s = 0;
#pragma unroll
    for (int i = 0; i < 3; i++) {
        bool adv = (id >= args.cnt[s]);
        if (adv) { id -= args.cnt[s]; s++; }
    }
    const __half* Ah = args.Ah[s];
    const __half* Al = args.Al[s];
    const __half* Bh = args.Bh[s];
    const __half* Bl = args.Bl[s];
    float* C0 = args.C0[s];
    float* C1 = args.C1[s];
    __half* Ho = args.Ho[s];
    const int nbx = args.nbx[s];
    const int bx = id % nbx, by = id / nbx;
    const int m0 = by * 128, n0 = bx * 128;

    const int tid = threadIdx.x;
    const int wid = tid >> 5, lane = tid & 31;
    const int wm = wid >> 2, wn = wid & 3;

    const uint32_t rowA = (uint32_t)(wm * 64 + (lane & 7) + ((lane >> 3) & 1) * 8);
    const uint32_t colA = (uint32_t)(((lane >> 4) & 1) * 16);
    const uint32_t oAh = rowA * 80 + colA;
    const uint32_t oAl = oAh + ABYTES;
    const uint32_t rowB = (uint32_t)(wn * 32 + (lane & 7));
    const uint32_t colB = (uint32_t)(((lane >> 3) & 1) * 16);
    const uint32_t oBh = 2 * ABYTES + rowB * 80 + colB;
    const uint32_t oBl = oBh + BBYTES;

    float acc[MT][4][4];
#pragma unroll
    for (int i = 0; i < MT; i++)
#pragma unroll
        for (int j = 0; j < 4; j++)
#pragma unroll
            for (int e = 0; e < 4; e++) acc[i][j][e] = 0.f;

    auto load_stage = [&](int st, int kc) {
        const int k0 = kc * 32;
        const uint32_t base = sb + st * STG;
#pragma unroll
        for (int i = 0; i < 2; i++) {
            int c = tid + i * 256;
            int r = c >> 2, qq = c & 3;
            uint32_t dst = base + r * 80 + qq * 16;
            const size_t ga = (size_t)(m0 + r) * 512 + k0 + qq * 8;
            cp16(dst, Ah + ga);
            if (Al) cp16(dst + ABYTES, Al + ga);
            uint32_t dstB = base + 2 * ABYTES + r * 80 + qq * 16;
            const size_t gb = (size_t)(n0 + r) * 512 + k0 + qq * 8;
            cp16(dstB, Bh + gb);
            cp16(dstB + BBYTES, Bl + gb);
        }
    };

    load_stage(0, 0); CP_COMMIT();
    load_stage(1, 1); CP_COMMIT();

    for (int kc = 0; kc < 16; kc++) {
        if (kc < 15) { CP_WAIT1(); } else { CP_WAIT0(); }
        __syncthreads();
        const uint32_t so = sb + (kc & 1) * STG;
#pragma unroll
        for (int ks = 0; ks < 2; ks++) {
            uint32_t bh[4][2], bl[4][2];
#pragma unroll
            for (int ni = 0; ni < 4; ni++) ldsm_x2(bh[ni], so + oBh + ni * 640 + ks * 32);
#pragma unroll
            for (int ni = 0; ni < 4; ni++) ldsm_x2(bl[ni], so + oBl + ni * 640 + ks * 32);
#pragma unroll
            for (int mi = 0; mi < MT; mi++) {
                uint32_t ah[4];
                ldsm_x4(ah, so + oAh + mi * 1280 + ks * 32);
#pragma unroll
                for (int ni = 0; ni < 4; ni++) mma16816(acc[mi][ni], ah, bh[ni]);
#pragma unroll
                for (int ni = 0; ni < 4; ni++) mma16816(acc[mi][ni], ah, bl[ni]);
                if (Al) {
                    uint32_t al[4];
                    ldsm_x4(al, so + oAl + mi * 1280 + ks * 32);
#pragma unroll
                    for (int ni = 0; ni < 4; ni++) mma16816(acc[mi][ni], al, bh[ni]);
                }
            }
        }
        __syncthreads();
        if (kc + 2 < 16) { load_stage(kc & 1, kc + 2); }
        CP_COMMIT();
    }

    const int mrow = m0 + wm * 64 + (lane >> 2);
    const int ncol = n0 + wn * 32 + (lane & 3) * 2;
#pragma unroll
    for (int mi = 0; mi < MT; mi++) {
#pragma unroll
        for (int ni = 0; ni < 4; ni++) {
            int col = ncol + ni * 8;
            int r0 = mrow + mi * 16;
            if (Ho) {
                *(__half2*)&Ho[(size_t)r0 * 512 + col] =
                    __floats2half2_rn(acc[mi][ni][0], acc[mi][ni][1]);
                *(__half2*)&Ho[(size_t)(r0 + 8) * 512 + col] =
                    __floats2half2_rn(acc[mi][ni][2], acc[mi][ni][3]);
            } else {
                float* dst = (C1 && col >= 512) ? (C1 + col - 512) : (C0 + col);
                *(float2*)&dst[(size_t)r0 * 512]       = make_float2(acc[mi][ni][0], acc[mi][ni][1]);
                *(float2*)&dst[(size_t)(r0 + 8) * 512] = make_float2(acc[mi][ni][2], acc[mi][ni][3]);
            }
        }
    }
}

// ---------------------------------------------------------------------------
// Fused hierarchical attention — coalesced; fp16 token-K/V.
// One block per (b,h,q), 128 threads (4 warps).
// ---------------------------------------------------------------------------
__global__ __launch_bounds__(128)
void attn_kernel(const int* __restrict__ valid_lens) {
    const int idx = blockIdx.x;
    const int q = idx & 63;
    const int h = (idx >> 6) & 7;
    const int b = idx >> 9;
    const int tid = threadIdx.x, wid = tid >> 5, lane = tid & 31;
    const float scale = 0.125f;

    __shared__ float qs[64], qt[64], sc[64];
    __shared__ int   sidx[8];
    __shared__ float svals[8];
    __shared__ float sw8[8];
    __shared__ float cw[128];
    __shared__ float pv[2][64];

    if (tid < 64) {
        qs[tid] = g_q_stat[(size_t)(b * 64 + q) * 512 + h * 64 + tid];
        qt[tid] = g_q_tok [(size_t)(b * 64 + q) * 512 + h * 64 + tid];
    }
    __syncthreads();

    const int vlen = valid_lens[b];

    // --- Phase A: stat scores (fp32, warp-cooperative, coalesced) ---
    {
        const float q0 = qs[lane], q1 = qs[lane + 32];
#pragma unroll
        for (int i = 0; i < 16; i++) {
            const int s = wid * 16 + i;
            const float* kp = &g_k_stat[(size_t)(b * 64 + s) * 512 + h * 64];
            float part = q0 * kp[lane] + q1 * kp[lane + 32];
#pragma unroll
            for (int o = 16; o; o >>= 1) part += __shfl_xor_sync(~0u, part, o);
            if (lane == 0) sc[s] = (s < vlen) ? part * scale : NEGV;
        }
    }
    __syncthreads();

    // --- Phase B: top-8 warp-parallel argmax (first-max tiebreak) ---
    if (wid == 0) {
        float v0 = sc[lane], v1 = sc[lane + 32];
        int i0 = lane, i1 = lane + 32;
#pragma unroll
        for (int j = 0; j < 8; j++) {
            float m; int mi;
            if (v0 >= v1) { m = v0; mi = i0; } else { m = v1; mi = i1; }
#pragma unroll
            for (int o = 16; o; o >>= 1) {
                float om = __shfl_xor_sync(~0u, m, o);
                int   oi = __shfl_xor_sync(~0u, mi, o);
                if (om > m || (om == m && oi < mi)) { m = om; mi = oi; }
            }
            if (lane == 0) { sidx[j] = mi; svals[j] = m; }
            if (i0 == mi) v0 = -3.0e38f;
            if (i1 == mi) v1 = -3.0e38f;
        }
        if (lane == 0) {
            const float m = svals[0];
            float e[8], sum = 0.f;
#pragma unroll
            for (int j = 0; j < 8; j++) { e[j] = expf(svals[j] - m); sum += e[j]; }
            const float inv = 1.f / sum;
#pragma unroll
            for (int j = 0; j < 8; j++) sw8[j] = e[j] * inv;
        }
    }
    __syncthreads();

    // --- Phase C: token scores (fp16 K, half2 loads: 1 transaction/row) ---
    {
        const float q0 = qt[2 * lane], q1 = qt[2 * lane + 1];
#pragma unroll
        for (int i = 0; i < 32; i++) {
            const int p = wid * 32 + i;
            const int j = p >> 4, t = p & 15;
            const int s = sidx[j];
            const __half2* kp = (const __half2*)&g_ktk16[(((size_t)(b * 64 + s)) * 16 + t) * 512 + h * 64];
            float2 k2 = __half22float2(kp[lane]);
            float part = q0 * k2.x + q1 * k2.y;
#pragma unroll
            for (int o = 16; o; o >>= 1) part += __shfl_xor_sync(~0u, part, o);
            if (lane == 0) cw[p] = part * scale;
        }
    }
    __syncthreads();

    // --- Phase D: per-segment token softmax fused with stat weight ---
    if (tid < 8) {
        const int j = tid;
        float m = cw[j * 16];
#pragma unroll
        for (int t = 1; t < 16; t++) m = fmaxf(m, cw[j * 16 + t]);
        float e[16], sum = 0.f;
#pragma unroll
        for (int t = 0; t < 16; t++) { e[t] = expf(cw[j * 16 + t] - m); sum += e[t]; }
        const float f = sw8[j] / sum;
#pragma unroll
        for (int t = 0; t < 16; t++) cw[j * 16 + t] = e[t] * f;
    }
    __syncthreads();

    // --- Phase E: weighted V reduction (fp16 V); j split across halves ---
    {
        const int half = tid >> 6, d = tid & 63;
        float acc = 0.f;
#pragma unroll
        for (int jj = 0; jj < 4; jj++) {
            const int j = half * 4 + jj;
            const int s = sidx[j];
            const __half* vp = &g_v16h[(((size_t)(b * 64 + s)) * 16) * 512 + h * 64 + d];
#pragma unroll
            for (int t = 0; t < 16; t++)
                acc = fmaf(cw[j * 16 + t], __half2float(vp[(size_t)t * 512]), acc);
        }
        pv[half][d] = acc;
    }
    __syncthreads();

    if (tid < 64) {
        const float r = pv[0][tid] + pv[1][tid];
        const size_t off = (size_t)(b * 64 + q) * 512 + h * 64 + tid;
        __half hh = __float2half(r);
        g_at_h[off] = hh;
        g_at_l[off] = __float2half(r - __half2float(hh));
    }
}

// ---------------------------------------------------------------------------
extern "C" void kernel_launch(void* const* d_in, const int* in_sizes, int n_in,
                              void* d_out, int out_size) {
    const float* queries        = (const float*)d_in[0];
    const float* stat_keys      = (const float*)d_in[1];
    const float* token_keys     = (const float*)d_in[2];
    const float* values         = (const float*)d_in[3];
    const int*   stat_valid_len = (const int*)  d_in[4];
    WPtrs ws;
    for (int i = 0; i < 6; i++) ws.p[i] = (const float*)d_in[5 + i];
    float* out = (float*)d_out;

    __half *cq_h, *cq_l, *csk_h, *csk_l, *ctk_h, *cv_h;
    __half *wh, *wl, *at_h, *at_l, *ktk16, *v16h;
    float *q_stat, *q_tok, *k_stat;
    cudaGetSymbolAddress((void**)&cq_h,  g_cq_h);  cudaGetSymbolAddress((void**)&cq_l,  g_cq_l);
    cudaGetSymbolAddress((void**)&csk_h, g_csk_h); cudaGetSymbolAddress((void**)&csk_l, g_csk_l);
    cudaGetSymbolAddress((void**)&ctk_h, g_ctk_h); cudaGetSymbolAddress((void**)&cv_h,  g_cv_h);
    cudaGetSymbolAddress((void**)&wh,    g_wh);    cudaGetSymbolAddress((void**)&wl,    g_wl);
    cudaGetSymbolAddress((void**)&at_h,  g_at_h);  cudaGetSymbolAddress((void**)&at_l,  g_at_l);
    cudaGetSymbolAddress((void**)&ktk16, g_ktk16); cudaGetSymbolAddress((void**)&v16h,  g_v16h);
    cudaGetSymbolAddress((void**)&q_stat, g_q_stat);
    cudaGetSymbolAddress((void**)&q_tok,  g_q_tok);
    cudaGetSymbolAddress((void**)&k_stat, g_k_stat);

    const size_t WSZ = (size_t)512 * 512;
    constexpr int SMEM = 2 * (2 * 128 * 80 + 2 * 128 * 80);  // 81920
    cudaFuncSetAttribute(gemm_batched, cudaFuncAttributeMaxDynamicSharedMemorySize, SMEM);

    // 1) prep
    prep_w<<<dim3(16, 16, 6), dim3(32, 8)>>>(ws);
    conv_act<<<dim3(4096, 4), 256>>>(queries, stat_keys, token_keys, values);

    // 2) all five projections in one launch (560 CTAs)
    GemmBatch gb;
    // seg 0: queries @ [Wq_stat|Wq_token] (3-term, fp32 split out)
    gb.Ah[0] = cq_h;  gb.Al[0] = cq_l;  gb.Bh[0] = wh;           gb.Bl[0] = wl;
    gb.C0[0] = q_stat; gb.C1[0] = q_tok; gb.Ho[0] = nullptr; gb.nbx[0] = 8; gb.cnt[0] = 32;
    // seg 1: stat_keys @ Wk_stat (3-term, fp32 out)
    gb.Ah[1] = csk_h; gb.Al[1] = csk_l; gb.Bh[1] = wh + 2 * WSZ; gb.Bl[1] = wl + 2 * WSZ;
    gb.C0[1] = k_stat; gb.C1[1] = nullptr; gb.Ho[1] = nullptr; gb.nbx[1] = 4; gb.cnt[1] = 16;
    // seg 2: token_keys16 @ Wk_token (2-term, fp16 out)
    gb.Ah[2] = ctk_h; gb.Al[2] = nullptr; gb.Bh[2] = wh + 3 * WSZ; gb.Bl[2] = wl + 3 * WSZ;
    gb.C0[2] = nullptr; gb.C1[2] = nullptr; gb.Ho[2] = ktk16; gb.nbx[2] = 4; gb.cnt[2] = 256;
    // seg 3: values16 @ Wv (2-term, fp16 out)
    gb.Ah[3] = cv_h;  gb.Al[3] = nullptr; gb.Bh[3] = wh + 4 * WSZ; gb.Bl[3] = wl + 4 * WSZ;
    gb.C0[3] = nullptr; gb.C1[3] = nullptr; gb.Ho[3] = v16h; gb.nbx[3] = 4; gb.cnt[3] = 256;
    gemm_batched<<<560, 256, SMEM>>>(gb);

    // 3) fused hierarchical attention
    attn_kernel<<<B_ * H_ * Q_, 128>>>(stat_valid_len);

    // 4) output projection (3-term, fp32 out)
    GemmBatch go;
    go.Ah[0] = at_h; go.Al[0] = at_l; go.Bh[0] = wh + 5 * WSZ; go.Bl[0] = wl + 5 * WSZ;
    go.C0[0] = out;  go.C1[0] = nullptr; go.Ho[0] = nullptr; go.nbx[0] = 4; go.cnt[0] = 16;
    go.cnt[1] = go.cnt[2] = go.cnt[3] = 0x7fffffff;
    go.Ah[1] = go.Ah[2] = go.Ah[3] = at_h; go.Al[1] = go.Al[2] = go.Al[3] = at_l;
    go.Bh[1] = go.Bh[2] = go.Bh[3] = wh;   go.Bl[1] = go.Bl[2] = go.Bl[3] = wl;
    go.C0[1] = go.C0[2] = go.C0[3] = out;  go.C1[1] = go.C1[2] = go.C1[3] = nullptr;
    go.Ho[1] = go.Ho[2] = go.Ho[3] = nullptr;
    go.nbx[1] = go.nbx[2] = go.nbx[3] = 4;
    gemm_batched<<<16, 256, SMEM>>>(go);
}

// round 9
// speedup vs baseline: 4.4172x; 1.2036x over previous
#include <cuda_runtime.h>
#include <cuda_fp16.h>
#include <cstdint>
#include <math.h>

#define B_   8
#define Q_   64
#define S_   64
#define T_   64
#define H_   8
#define DH_  64
#define NH_  512
#define NEGV (-1e6f)

// ---------------------------------------------------------------------------
// Scratch (device globals)
// ---------------------------------------------------------------------------
__device__ __half g_cq_h [512 * 512],  g_cq_l [512 * 512];    // queries hi/lo
__device__ __half g_csk_h[512 * 512],  g_csk_l[512 * 512];    // stat_keys hi/lo
__device__ __half g_ctk_h[8192 * 512];                        // gathered token_keys (hi only)
__device__ __half g_cv_h [8192 * 512];                        // gathered values (hi only)
__device__ __half g_wh[6 * 512 * 512], g_wl[6 * 512 * 512];   // W^T [N,K] fp16 hi/lo
__device__ float g_q_stat[512 * 512];
__device__ float g_q_tok [512 * 512];
__device__ float g_k_stat[512 * 512];
__device__ __half g_ktk16[8192 * 512];                        // projected token keys (fp16)
__device__ __half g_v16h [8192 * 512];                        // projected values (fp16)
__device__ __half g_at_h[512 * 512], g_at_l[512 * 512];       // attn out fp16 hi/lo

// ---------------------------------------------------------------------------
// helpers
// ---------------------------------------------------------------------------
__device__ __forceinline__ uint32_t smem_u32(const void* p) {
    uint32_t a;
    asm("{ .reg .u64 t; cvta.to.shared.u64 t, %1; cvt.u32.u64 %0, t; }" : "=r"(a) : "l"(p));
    return a;
}
__device__ __forceinline__ void ldsm_x4(uint32_t* r, uint32_t addr) {
    asm volatile("ldmatrix.sync.aligned.m8n8.x4.shared.b16 {%0,%1,%2,%3}, [%4];"
        : "=r"(r[0]), "=r"(r[1]), "=r"(r[2]), "=r"(r[3]) : "r"(addr));
}
__device__ __forceinline__ void ldsm_x2(uint32_t* r, uint32_t addr) {
    asm volatile("ldmatrix.sync.aligned.m8n8.x2.shared.b16 {%0,%1}, [%2];"
        : "=r"(r[0]), "=r"(r[1]) : "r"(addr));
}
__device__ __forceinline__ void mma16816(float* d, const uint32_t* a, const uint32_t* b) {
    asm volatile("mma.sync.aligned.m16n8k16.row.col.f32.f16.f16.f32 "
        "{%0,%1,%2,%3}, {%4,%5,%6,%7}, {%8,%9}, {%0,%1,%2,%3};"
        : "+f"(d[0]), "+f"(d[1]), "+f"(d[2]), "+f"(d[3])
        : "r"(a[0]), "r"(a[1]), "r"(a[2]), "r"(a[3]), "r"(b[0]), "r"(b[1]));
}
__device__ __forceinline__ void cp16(uint32_t dst, const void* src) {
    asm volatile("cp.async.cg.shared.global [%0], [%1], 16;" :: "r"(dst), "l"(src));
}
#define CP_COMMIT() asm volatile("cp.async.commit_group;" ::: "memory")
#define CP_WAIT1()  asm volatile("cp.async.wait_group 1;" ::: "memory")
#define CP_WAIT0()  asm volatile("cp.async.wait_group 0;" ::: "memory")

// ---------------------------------------------------------------------------
// Convert inputs: q/sk -> fp16 hi/lo; gathered tk/v -> fp16 hi only
// ---------------------------------------------------------------------------
__global__ __launch_bounds__(256)
void conv_act(const float* __restrict__ q, const float* __restrict__ sk,
              const float* __restrict__ tk, const float* __restrict__ v) {
    const int z = blockIdx.y;
    const int rows = (z < 2) ? 512 : 8192;
    const int idx = blockIdx.x * 256 + threadIdx.x;
    if (idx >= rows * 128) return;
    const int r = idx >> 7, c4 = idx & 127;

    if (z < 2) {
        const float* src = z ? sk : q;
        __half* dh = z ? g_csk_h : g_cq_h;
        __half* dl = z ? g_csk_l : g_cq_l;
        float4 x = *(const float4*)&src[(size_t)r * 512 + c4 * 4];
        __half h0 = __float2half(x.x), h1 = __float2half(x.y),
               h2 = __float2half(x.z), h3 = __float2half(x.w);
        __half l0 = __float2half(x.x - __half2float(h0)),
               l1 = __float2half(x.y - __half2float(h1)),
               l2 = __float2half(x.z - __half2float(h2)),
               l3 = __float2half(x.w - __half2float(h3));
        uint2 hh, ll;
        hh.x = (uint32_t)__half_as_ushort(h0) | ((uint32_t)__half_as_ushort(h1) << 16);
        hh.y = (uint32_t)__half_as_ushort(h2) | ((uint32_t)__half_as_ushort(h3) << 16);
        ll.x = (uint32_t)__half_as_ushort(l0) | ((uint32_t)__half_as_ushort(l1) << 16);
        ll.y = (uint32_t)__half_as_ushort(l2) | ((uint32_t)__half_as_ushort(l3) << 16);
        *(uint2*)&dh[(size_t)r * 512 + c4 * 4] = hh;
        *(uint2*)&dl[(size_t)r * 512 + c4 * 4] = ll;
    } else {
        const int sr = (r >> 4) * 64 + 48 + (r & 15);
        const float* src = (z == 2) ? tk : v;
        __half* dh = (z == 2) ? g_ctk_h : g_cv_h;
        float4 x = *(const float4*)&src[(size_t)sr * 512 + c4 * 4];
        uint2 hh;
        hh.x = (uint32_t)__half_as_ushort(__float2half(x.x)) |
               ((uint32_t)__half_as_ushort(__float2half(x.y)) << 16);
        hh.y = (uint32_t)__half_as_ushort(__float2half(x.z)) |
               ((uint32_t)__half_as_ushort(__float2half(x.w)) << 16);
        *(uint2*)&dh[(size_t)r * 512 + c4 * 4] = hh;
    }
}

// ---------------------------------------------------------------------------
// Weight prep: transpose W[K,N] fp32 -> Wt[N,K] fp16 hi/lo (6 weights)
// ---------------------------------------------------------------------------
struct WPtrs { const float* p[6]; };

__global__ __launch_bounds__(256)
void prep_w(WPtrs ws) {
    __shared__ float t[32][33];
    const int widx = blockIdx.z;
    const float* W = ws.p[widx];
    __half* hiw = g_wh + (size_t)widx * 512 * 512;
    __half* low = g_wl + (size_t)widx * 512 * 512;
    const int n0 = blockIdx.x * 32, k0 = blockIdx.y * 32;
    const int tx = threadIdx.x, ty = threadIdx.y;
#pragma unroll
    for (int i = ty; i < 32; i += 8)
        t[i][tx] = W[(size_t)(k0 + i) * 512 + n0 + tx];
    __syncthreads();
#pragma unroll
    for (int i = ty; i < 32; i += 8) {
        float v = t[tx][i];
        __half h = __float2half(v);
        hiw[(size_t)(n0 + i) * 512 + k0 + tx] = h;
        low[(size_t)(n0 + i) * 512 + k0 + tx] = __float2half(v - __half2float(h));
    }
}

// ---------------------------------------------------------------------------
// Batched fp16 hi/lo GEMM, cp.async 2-stage pipeline (round 8, passing)
// ---------------------------------------------------------------------------
struct GemmBatch {
    const __half *Ah[4], *Al[4], *Bh[4], *Bl[4];
    float *C0[4], *C1[4];
    __half *Ho[4];
    int nbx[4];
    int cnt[4];
};

__global__ __launch_bounds__(256)
void gemm_batched(GemmBatch args) {
    constexpr int MT = 4;
    constexpr uint32_t ABYTES = 128 * 80;
    constexpr uint32_t BBYTES = 128 * 80;
    constexpr uint32_t STG    = 2 * ABYTES + 2 * BBYTES;
    extern __shared__ char smem[];
    const uint32_t sb = smem_u32(smem);

    int id = blockIdx.x, s = 0;
#pragma unroll
    for (int i = 0; i < 3; i++) {
        bool adv = (id >= args.cnt[s]);
        if (adv) { id -= args.cnt[s]; s++; }
    }
    const __half* Ah = args.Ah[s];
    const __half* Al = args.Al[s];
    const __half* Bh = args.Bh[s];
    const __half* Bl = args.Bl[s];
    float* C0 = args.C0[s];
    float* C1 = args.C1[s];
    __half* Ho = args.Ho[s];
    const int nbx = args.nbx[s];
    const int bx = id % nbx, by = id / nbx;
    const int m0 = by * 128, n0 = bx * 128;

    const int tid = threadIdx.x;
    const int wid = tid >> 5, lane = tid & 31;
    const int wm = wid >> 2, wn = wid & 3;

    const uint32_t rowA = (uint32_t)(wm * 64 + (lane & 7) + ((lane >> 3) & 1) * 8);
    const uint32_t colA = (uint32_t)(((lane >> 4) & 1) * 16);
    const uint32_t oAh = rowA * 80 + colA;
    const uint32_t oAl = oAh + ABYTES;
    const uint32_t rowB = (uint32_t)(wn * 32 + (lane & 7));
    const uint32_t colB = (uint32_t)(((lane >> 3) & 1) * 16);
    const uint32_t oBh = 2 * ABYTES + rowB * 80 + colB;
    const uint32_t oBl = oBh + BBYTES;

    float acc[MT][4][4];
#pragma unroll
    for (int i = 0; i < MT; i++)
#pragma unroll
        for (int j = 0; j < 4; j++)
#pragma unroll
            for (int e = 0; e < 4; e++) acc[i][j][e] = 0.f;

    auto load_stage = [&](int st, int kc) {
        const int k0 = kc * 32;
        const uint32_t base = sb + st * STG;
#pragma unroll
        for (int i = 0; i < 2; i++) {
            int c = tid + i * 256;
            int r = c >> 2, qq = c & 3;
            uint32_t dst = base + r * 80 + qq * 16;
            const size_t ga = (size_t)(m0 + r) * 512 + k0 + qq * 8;
            cp16(dst, Ah + ga);
            if (Al) cp16(dst + ABYTES, Al + ga);
            uint32_t dstB = base + 2 * ABYTES + r * 80 + qq * 16;
            const size_t gb = (size_t)(n0 + r) * 512 + k0 + qq * 8;
            cp16(dstB, Bh + gb);
            cp16(dstB + BBYTES, Bl + gb);
        }
    };

    load_stage(0, 0); CP_COMMIT();
    load_stage(1, 1); CP_COMMIT();

    for (int kc = 0; kc < 16; kc++) {
        if (kc < 15) { CP_WAIT1(); } else { CP_WAIT0(); }
        __syncthreads();
        const uint32_t so = sb + (kc & 1) * STG;
#pragma unroll
        for (int ks = 0; ks < 2; ks++) {
            uint32_t bh[4][2], bl[4][2];
#pragma unroll
            for (int ni = 0; ni < 4; ni++) ldsm_x2(bh[ni], so + oBh + ni * 640 + ks * 32);
#pragma unroll
            for (int ni = 0; ni < 4; ni++) ldsm_x2(bl[ni], so + oBl + ni * 640 + ks * 32);
#pragma unroll
            for (int mi = 0; mi < MT; mi++) {
                uint32_t ah[4];
                ldsm_x4(ah, so + oAh + mi * 1280 + ks * 32);
#pragma unroll
                for (int ni = 0; ni < 4; ni++) mma16816(acc[mi][ni], ah, bh[ni]);
#pragma unroll
                for (int ni = 0; ni < 4; ni++) mma16816(acc[mi][ni], ah, bl[ni]);
                if (Al) {
                    uint32_t al[4];
                    ldsm_x4(al, so + oAl + mi * 1280 + ks * 32);
#pragma unroll
                    for (int ni = 0; ni < 4; ni++) mma16816(acc[mi][ni], al, bh[ni]);
                }
            }
        }
        __syncthreads();
        if (kc + 2 < 16) { load_stage(kc & 1, kc + 2); }
        CP_COMMIT();
    }

    const int mrow = m0 + wm * 64 + (lane >> 2);
    const int ncol = n0 + wn * 32 + (lane & 3) * 2;
#pragma unroll
    for (int mi = 0; mi < MT; mi++) {
#pragma unroll
        for (int ni = 0; ni < 4; ni++) {
            int col = ncol + ni * 8;
            int r0 = mrow + mi * 16;
            if (Ho) {
                *(__half2*)&Ho[(size_t)r0 * 512 + col] =
                    __floats2half2_rn(acc[mi][ni][0], acc[mi][ni][1]);
                *(__half2*)&Ho[(size_t)(r0 + 8) * 512 + col] =
                    __floats2half2_rn(acc[mi][ni][2], acc[mi][ni][3]);
            } else {
                float* dst = (C1 && col >= 512) ? (C1 + col - 512) : (C0 + col);
                *(float2*)&dst[(size_t)r0 * 512]       = make_float2(acc[mi][ni][0], acc[mi][ni][1]);
                *(float2*)&dst[(size_t)(r0 + 8) * 512] = make_float2(acc[mi][ni][2], acc[mi][ni][3]);
            }
        }
    }
}

// ---------------------------------------------------------------------------
// Hierarchical attention v2: one block per (b, h, q-half=32 queries).
// Stages k_stat^T, q_stat, q_tok (fp32) and the full token-K tile (fp16,
// pitch 66 halves = 33 words, conflict-free) in smem; V tile reuses the
// token-K buffer. No per-dot shfl reductions except one per token dot.
// ---------------------------------------------------------------------------
#define ATTN_SMEM 195584

__global__ __launch_bounds__(512)
void attn2(const int* __restrict__ valid_lens) {
    extern __shared__ char sm[];
    __half* kv   = (__half*)sm;                                 // [1024][66]
    float*  ks_t = (float*)(sm + 135168);                       // [64][68] (d-major)
    float*  qs   = (float*)(sm + 135168 + 17408);               // [32][64]
    float*  qt   = qs + 2048;                                   // [32][64]
    float*  sc   = qt + 2048;                                   // [32][64]
    float*  cw   = sc + 2048;                                   // [32][128]
    int*    sidx = (int*)(cw + 4096);                           // [32][8]
    float*  sw8  = (float*)(sidx + 256);                        // [32][8]

    const int bh = blockIdx.x;
    const int b = bh >> 3, h = bh & 7;
    const int qh = blockIdx.y;
    const int qbase = b * 64 + qh * 32;
    const int tid = threadIdx.x, wid = tid >> 5, lane = tid & 31;
    const float scale = 0.125f;

    // ---- stage k_stat (transposed), q_stat, q_tok, token-K ----
#pragma unroll
    for (int k = 0; k < 2; k++) {
        int i4 = tid + k * 512;
        int s = i4 >> 4, dq = i4 & 15;
        float4 v = *(const float4*)&g_k_stat[(size_t)(b * 64 + s) * 512 + h * 64 + dq * 4];
        ks_t[(dq * 4 + 0) * 68 + s] = v.x;
        ks_t[(dq * 4 + 1) * 68 + s] = v.y;
        ks_t[(dq * 4 + 2) * 68 + s] = v.z;
        ks_t[(dq * 4 + 3) * 68 + s] = v.w;
    }
    {
        int q = tid >> 4, dq = tid & 15;
        *(float4*)&qs[q * 64 + dq * 4] =
            *(const float4*)&g_q_stat[(size_t)(qbase + q) * 512 + h * 64 + dq * 4];
        *(float4*)&qt[q * 64 + dq * 4] =
            *(const float4*)&g_q_tok[(size_t)(qbase + q) * 512 + h * 64 + dq * 4];
    }
#pragma unroll
    for (int k = 0; k < 16; k++) {
        int idx = tid + k * 512;
        int r = idx >> 3, c = idx & 7;
        uint4 v = *(const uint4*)&g_ktk16[((size_t)(b * 1024) + r) * 512 + h * 64 + c * 8];
        uint32_t* dst = (uint32_t*)kv + r * 33 + c * 4;
        dst[0] = v.x; dst[1] = v.y; dst[2] = v.z; dst[3] = v.w;
    }
    __syncthreads();

    const int vlen = valid_lens[b];

    // ---- Phase A: stat scores (per-thread 4-s register block, smem only) ----
    {
        const int q = tid >> 4, sg = tid & 15;
        float a0 = 0.f, a1 = 0.f, a2 = 0.f, a3 = 0.f;
        const float* qrow = &qs[q * 64];
#pragma unroll
        for (int d = 0; d < 64; d++) {
            float qv = qrow[d];
            float4 kf = *(const float4*)&ks_t[d * 68 + sg * 4];
            a0 = fmaf(qv, kf.x, a0);
            a1 = fmaf(qv, kf.y, a1);
            a2 = fmaf(qv, kf.z, a2);
            a3 = fmaf(qv, kf.w, a3);
        }
        const int s0 = sg * 4;
        sc[q * 64 + s0 + 0] = (s0 + 0 < vlen) ? a0 * scale : NEGV;
        sc[q * 64 + s0 + 1] = (s0 + 1 < vlen) ? a1 * scale : NEGV;
        sc[q * 64 + s0 + 2] = (s0 + 2 < vlen) ? a2 * scale : NEGV;
        sc[q * 64 + s0 + 3] = (s0 + 3 < vlen) ? a3 * scale : NEGV;
    }
    __syncthreads();

    // ---- Phase B: top-8 per query (2 queries per warp) ----
    for (int rep = 0; rep < 2; rep++) {
        const int q = wid * 2 + rep;
        float v0 = sc[q * 64 + lane], v1 = sc[q * 64 + lane + 32];
        int i0 = lane, i1 = lane + 32;
        float vals[8];
#pragma unroll
        for (int j = 0; j < 8; j++) {
            float m; int mi;
            if (v0 >= v1) { m = v0; mi = i0; } else { m = v1; mi = i1; }
#pragma unroll
            for (int o = 16; o; o >>= 1) {
                float om = __shfl_xor_sync(~0u, m, o);
                int   oi = __shfl_xor_sync(~0u, mi, o);
                if (om > m || (om == m && oi < mi)) { m = om; mi = oi; }
            }
            if (lane == 0) { sidx[q * 8 + j] = mi; vals[j] = m; }
            if (i0 == mi) v0 = -3.0e38f;
            if (i1 == mi) v1 = -3.0e38f;
        }
        if (lane == 0) {
            const float m = vals[0];
            float e[8], sum = 0.f;
#pragma unroll
            for (int j = 0; j < 8; j++) { e[j] = expf(vals[j] - m); sum += e[j]; }
            const float inv = 1.f / sum;
#pragma unroll
            for (int j = 0; j < 8; j++) sw8[q * 8 + j] = e[j] * inv;
        }
    }
    __syncthreads();

    // ---- Phase C: token scores (lane-pair per dot, fp16 K from smem) ----
    {
        const int t = lane >> 1, hf = lane & 1;
        for (int kk = 0; kk < 16; kk++) {
            const int q = wid * 2 + (kk >> 3);
            const int j = kk & 7;
            const int row = sidx[q * 8 + j] * 16 + t;
            const uint32_t* kr = (const uint32_t*)kv + row * 33 + hf * 16;
            const float* qr = &qt[q * 64 + hf * 32];
            float acc = 0.f;
#pragma unroll
            for (int it = 0; it < 16; it++) {
                float2 kf = __half22float2(*(const __half2*)&kr[it]);
                float2 q2 = *(const float2*)&qr[it * 2];
                acc = fmaf(q2.x, kf.x, acc);
                acc = fmaf(q2.y, kf.y, acc);
            }
            acc += __shfl_xor_sync(~0u, acc, 1);
            if (hf == 0) cw[q * 128 + j * 16 + t] = acc * scale;
        }
    }
    __syncthreads();

    // ---- stage V tile (overwrites kv) + Phase D softmax concurrently ----
#pragma unroll
    for (int k = 0; k < 16; k++) {
        int idx = tid + k * 512;
        int r = idx >> 3, c = idx & 7;
        uint4 v = *(const uint4*)&g_v16h[((size_t)(b * 1024) + r) * 512 + h * 64 + c * 8];
        uint32_t* dst = (uint32_t*)kv + r * 33 + c * 4;
        dst[0] = v.x; dst[1] = v.y; dst[2] = v.z; dst[3] = v.w;
    }
    if (tid < 256) {
        const int q = tid >> 3, j = tid & 7;
        float* c = &cw[q * 128 + j * 16];
        float m = c[0];
#pragma unroll
        for (int t = 1; t < 16; t++) m = fmaxf(m, c[t]);
        float e[16], sum = 0.f;
#pragma unroll
        for (int t = 0; t < 16; t++) { e[t] = expf(c[t] - m); sum += e[t]; }
        const float f = sw8[q * 8 + j] / sum;
#pragma unroll
        for (int t = 0; t < 16; t++) c[t] = e[t] * f;
    }
    __syncthreads();

    // ---- Phase E: weighted V reduction (per-thread 4 outputs) ----
    {
        const int q = tid >> 4, dg = tid & 15;
        float a0 = 0.f, a1 = 0.f, b0 = 0.f, b1 = 0.f;
#pragma unroll
        for (int j = 0; j < 8; j++) {
            const int rbase = sidx[q * 8 + j] * 16;
            const float* cwr = &cw[q * 128 + j * 16];
#pragma unroll
            for (int t = 0; t < 16; t++) {
                const float w = cwr[t];
                const uint32_t* vr = (const uint32_t*)kv + (rbase + t) * 33;
                float2 va = __half22float2(*(const __half2*)&vr[dg]);
                float2 vb = __half22float2(*(const __half2*)&vr[dg + 16]);
                a0 = fmaf(w, va.x, a0);
                a1 = fmaf(w, va.y, a1);
                b0 = fmaf(w, vb.x, b0);
                b1 = fmaf(w, vb.y, b1);
            }
        }
        const size_t off = (size_t)(qbase + q) * 512 + h * 64;
        __half ha0 = __float2half(a0), ha1 = __float2half(a1);
        __half hb0 = __float2half(b0), hb1 = __float2half(b1);
        *(__half2*)&g_at_h[off + 2 * dg]      = __halves2half2(ha0, ha1);
        *(__half2*)&g_at_h[off + 32 + 2 * dg] = __halves2half2(hb0, hb1);
        *(__half2*)&g_at_l[off + 2 * dg] = __halves2half2(
            __float2half(a0 - __half2float(ha0)), __float2half(a1 - __half2float(ha1)));
        *(__half2*)&g_at_l[off + 32 + 2 * dg] = __halves2half2(
            __float2half(b0 - __half2float(hb0)), __float2half(b1 - __half2float(hb1)));
    }
}

// ---------------------------------------------------------------------------
extern "C" void kernel_launch(void* const* d_in, const int* in_sizes, int n_in,
                              void* d_out, int out_size) {
    const float* queries        = (const float*)d_in[0];
    const float* stat_keys      = (const float*)d_in[1];
    const float* token_keys     = (const float*)d_in[2];
    const float* values         = (const float*)d_in[3];
    const int*   stat_valid_len = (const int*)  d_in[4];
    WPtrs ws;
    for (int i = 0; i < 6; i++) ws.p[i] = (const float*)d_in[5 + i];
    float* out = (float*)d_out;

    __half *cq_h, *cq_l, *csk_h, *csk_l, *ctk_h, *cv_h;
    __half *wh, *wl, *at_h, *at_l, *ktk16, *v16h;
    float *q_stat, *q_tok, *k_stat;
    cudaGetSymbolAddress((void**)&cq_h,  g_cq_h);  cudaGetSymbolAddress((void**)&cq_l,  g_cq_l);
    cudaGetSymbolAddress((void**)&csk_h, g_csk_h); cudaGetSymbolAddress((void**)&csk_l, g_csk_l);
    cudaGetSymbolAddress((void**)&ctk_h, g_ctk_h); cudaGetSymbolAddress((void**)&cv_h,  g_cv_h);
    cudaGetSymbolAddress((void**)&wh,    g_wh);    cudaGetSymbolAddress((void**)&wl,    g_wl);
    cudaGetSymbolAddress((void**)&at_h,  g_at_h);  cudaGetSymbolAddress((void**)&at_l,  g_at_l);
    cudaGetSymbolAddress((void**)&ktk16, g_ktk16); cudaGetSymbolAddress((void**)&v16h,  g_v16h);
    cudaGetSymbolAddress((void**)&q_stat, g_q_stat);
    cudaGetSymbolAddress((void**)&q_tok,  g_q_tok);
    cudaGetSymbolAddress((void**)&k_stat, g_k_stat);

    const size_t WSZ = (size_t)512 * 512;
    constexpr int SMEM = 2 * (2 * 128 * 80 + 2 * 128 * 80);  // 81920
    cudaFuncSetAttribute(gemm_batched, cudaFuncAttributeMaxDynamicSharedMemorySize, SMEM);
    cudaFuncSetAttribute(attn2, cudaFuncAttributeMaxDynamicSharedMemorySize, ATTN_SMEM);

    // 1) prep
    prep_w<<<dim3(16, 16, 6), dim3(32, 8)>>>(ws);
    conv_act<<<dim3(4096, 4), 256>>>(queries, stat_keys, token_keys, values);

    // 2) all five projections in one launch (560 CTAs)
    GemmBatch gb;
    gb.Ah[0] = cq_h;  gb.Al[0] = cq_l;  gb.Bh[0] = wh;           gb.Bl[0] = wl;
    gb.C0[0] = q_stat; gb.C1[0] = q_tok; gb.Ho[0] = nullptr; gb.nbx[0] = 8; gb.cnt[0] = 32;
    gb.Ah[1] = csk_h; gb.Al[1] = csk_l; gb.Bh[1] = wh + 2 * WSZ; gb.Bl[1] = wl + 2 * WSZ;
    gb.C0[1] = k_stat; gb.C1[1] = nullptr; gb.Ho[1] = nullptr; gb.nbx[1] = 4; gb.cnt[1] = 16;
    gb.Ah[2] = ctk_h; gb.Al[2] = nullptr; gb.Bh[2] = wh + 3 * WSZ; gb.Bl[2] = wl + 3 * WSZ;
    gb.C0[2] = nullptr; gb.C1[2] = nullptr; gb.Ho[2] = ktk16; gb.nbx[2] = 4; gb.cnt[2] = 256;
    gb.Ah[3] = cv_h;  gb.Al[3] = nullptr; gb.Bh[3] = wh + 4 * WSZ; gb.Bl[3] = wl + 4 * WSZ;
    gb.C0[3] = nullptr; gb.C1[3] = nullptr; gb.Ho[3] = v16h; gb.nbx[3] = 4; gb.cnt[3] = 256;
    gemm_batched<<<560, 256, SMEM>>>(gb);

    // 3) attention v2: 128 blocks, 512 threads, ~191KB smem
    attn2<<<dim3(64, 2), 512, ATTN_SMEM>>>(stat_valid_len);

    // 4) output projection
    GemmBatch go;
    go.Ah[0] = at_h; go.Al[0] = at_l; go.Bh[0] = wh + 5 * WSZ; go.Bl[0] = wl + 5 * WSZ;
    go.C0[0] = out;  go.C1[0] = nullptr; go.Ho[0] = nullptr; go.nbx[0] = 4; go.cnt[0] = 16;
    go.cnt[1] = go.cnt[2] = go.cnt[3] = 0x7fffffff;
    go.Ah[1] = go.Ah[2] = go.Ah[3] = at_h; go.Al[1] = go.Al[2] = go.Al[3] = at_l;
    go.Bh[1] = go.Bh[2] = go.Bh[3] = wh;   go.Bl[1] = go.Bl[2] = go.Bl[3] = wl;
    go.C0[1] = go.C0[2] = go.C0[3] = out;  go.C1[1] = go.C1[2] = go.C1[3] = nullptr;
    go.Ho[1] = go.Ho[2] = go.Ho[3] = nullptr;
    go.nbx[1] = go.nbx[2] = go.nbx[3] = 4;
    gemm_batched<<<16, 256, SMEM>>>(go);
}